// round 14
// baseline (speedup 1.0000x reference)
#include <cuda_runtime.h>
#include <cuda_bf16.h>
#include <math.h>
#include <stdint.h>

#define N_NODES 10000
#define N_EDGES 160000
#define NF 128
#define NB 20
#define NLAYERS 3
#define CUTOFF_R 5.0f

typedef __nv_bfloat16 bf16;

// ---------------- device scratch ----------------
__device__ float g_dist[(size_t)N_EDGES * NB];
__device__ float g_dir[(size_t)N_EDGES * 3];
__device__ float g_h[(size_t)N_NODES * NF];
__device__ float g_p1[(size_t)N_EDGES * NF];
__device__ float g_p2[(size_t)N_EDGES * NF];
__device__ float g_forceA[(size_t)N_NODES * 3 * NF];     // ping-pong force buffer
__device__ float g_force_fb[(size_t)N_NODES * 3 * NF];   // fallback if out buffer small
__device__ bf16 g_bhi1[(size_t)N_EDGES * NF];
__device__ bf16 g_blo1[(size_t)N_EDGES * NF];
__device__ bf16 g_bhi2[(size_t)N_NODES * 3 * NF];
__device__ bf16 g_blo2[(size_t)N_NODES * 3 * NF];
__device__ bf16 g_whi[21 * 16384];
__device__ bf16 g_wlo[21 * 16384];
// CSR
__device__ int g_cnt[N_NODES];
__device__ int g_off[N_NODES];
__device__ int g_rptr[N_NODES + 1];
__device__ int g_si[N_EDGES];
__device__ int g_sj[N_EDGES];

// ============================ helpers ============================
__device__ __forceinline__ uint32_t smem_u32(const void* p) {
    uint32_t a;
    asm("{ .reg .u64 t; cvta.to.shared.u64 t, %1; cvt.u32.u64 %0, t; }" : "=r"(a) : "l"(p));
    return a;
}
__device__ __forceinline__ void ldsm_x4(uint32_t* r, uint32_t addr) {
    asm volatile("ldmatrix.sync.aligned.m8n8.x4.shared.b16 {%0,%1,%2,%3}, [%4];"
                 : "=r"(r[0]), "=r"(r[1]), "=r"(r[2]), "=r"(r[3]) : "r"(addr));
}
__device__ __forceinline__ void mma_bf16(float* d, const uint32_t* a, uint32_t b0, uint32_t b1) {
    asm volatile(
        "mma.sync.aligned.m16n8k16.row.col.f32.bf16.bf16.f32 "
        "{%0,%1,%2,%3},{%4,%5,%6,%7},{%8,%9},{%0,%1,%2,%3};"
        : "+f"(d[0]), "+f"(d[1]), "+f"(d[2]), "+f"(d[3])
        : "r"(a[0]), "r"(a[1]), "r"(a[2]), "r"(a[3]), "r"(b0), "r"(b1));
}
__device__ __forceinline__ void split_bf16(float v, bf16& h, bf16& l) {
    h = __float2bfloat16(v);
    l = __float2bfloat16(v - __bfloat162float(h));
}

// ---------------- CSR build ----------------
__global__ void count_k(const int* __restrict__ ei, int* __restrict__ cnt)
{
    int e = blockIdx.x * blockDim.x + threadIdx.x;
    if (e < N_EDGES) atomicAdd(&cnt[ei[e]], 1);
}

__global__ void scan_k(const int* __restrict__ cnt, int* __restrict__ rptr)
{
    __shared__ int part[1024];
    const int tid = threadIdx.x;
    const int base = tid * 10;            // 1024*10 = 10240 >= 10000
    int loc[10];
    int s = 0;
    #pragma unroll
    for (int q = 0; q < 10; q++) {
        int idx = base + q;
        int c = (idx < N_NODES) ? cnt[idx] : 0;
        loc[q] = s; s += c;
    }
    part[tid] = s;
    __syncthreads();
    for (int off = 1; off < 1024; off <<= 1) {
        int v = (tid >= off) ? part[tid - off] : 0;
        __syncthreads();
        part[tid] += v;
        __syncthreads();
    }
    int pre = (tid == 0) ? 0 : part[tid - 1];
    #pragma unroll
    for (int q = 0; q < 10; q++) {
        int idx = base + q;
        if (idx < N_NODES) rptr[idx] = pre + loc[q];
    }
    if (tid == 1023) rptr[N_NODES] = part[1023];
}

__global__ void place_k(const int* __restrict__ ei, const int* __restrict__ rptr,
                        int* __restrict__ off, int* __restrict__ si, int* __restrict__ sj)
{
    int e = blockIdx.x * blockDim.x + threadIdx.x;
    if (e >= N_EDGES) return;
    int i = ei[e], j = ei[N_EDGES + e];
    int p = rptr[i] + atomicAdd(&off[i], 1);
    si[p] = i; sj[p] = j;
}

// ---------------- weight prep (all 21 matrices in one launch) ----------------
#define PREP_SM (2 * 128 * 136 * 2)
__global__ void prep_all_k(const float* __restrict__ W1, const float* __restrict__ W2,
                           const float* __restrict__ W3, const float* __restrict__ W4,
                           const float* __restrict__ W5, const float* __restrict__ W6,
                           const float* __restrict__ W7,
                           bf16* __restrict__ dhi, bf16* __restrict__ dlo)
{
    extern __shared__ char sm[];
    bf16* shi = (bf16*)sm;
    bf16* slo = (bf16*)(sm + 128 * 136 * 2);
    const int tid = threadIdx.x;
    const int fam = blockIdx.x / 3;       // 0..6
    const int lyr = blockIdx.x % 3;
    const float* srcs[7] = {W1, W2, W3, W4, W5, W6, W7};
    const float4* s4 = reinterpret_cast<const float4*>(srcs[fam] + (size_t)lyr * 16384);
    #pragma unroll 4
    for (int q = 0; q < 16; q++) {
        int lin = q * 256 + tid;
        int k = lin >> 5, n4 = (lin & 31) << 2;
        float4 v = s4[lin];
        float vv[4] = {v.x, v.y, v.z, v.w};
        #pragma unroll
        for (int t = 0; t < 4; t++) {
            bf16 hb, lb; split_bf16(vv[t], hb, lb);
            shi[(n4 + t) * 136 + k] = hb;
            slo[(n4 + t) * 136 + k] = lb;
        }
    }
    __syncthreads();
    size_t dslot = (size_t)(lyr * 7 + fam) * 16384;
    uint4* dh4 = reinterpret_cast<uint4*>(dhi + dslot);
    uint4* dl4 = reinterpret_cast<uint4*>(dlo + dslot);
    const char* smc = sm;
    #pragma unroll 4
    for (int q = 0; q < 8; q++) {
        int lin = q * 256 + tid;
        int row = lin >> 4, seg = lin & 15;
        dh4[lin] = *(const uint4*)(smc + row * 272 + seg * 16);
        dl4[lin] = *(const uint4*)(smc + 128 * 136 * 2 + row * 272 + seg * 16);
    }
}

// ---------------- fp32 -> bf16 hi/lo ----------------
__global__ void conv_k(const float* __restrict__ x, bf16* __restrict__ hi,
                       bf16* __restrict__ lo, int n4)
{
    int i = blockIdx.x * blockDim.x + threadIdx.x;
    if (i >= n4) return;
    float4 v = reinterpret_cast<const float4*>(x)[i];
    float vv[4] = {v.x, v.y, v.z, v.w};
    uint16_t h[4], l[4];
    #pragma unroll
    for (int t = 0; t < 4; t++) {
        bf16 hb, lb; split_bf16(vv[t], hb, lb);
        h[t] = __bfloat16_as_ushort(hb); l[t] = __bfloat16_as_ushort(lb);
    }
    reinterpret_cast<uint2*>(hi)[i] = make_uint2((uint32_t)h[0] | ((uint32_t)h[1] << 16),
                                                 (uint32_t)h[2] | ((uint32_t)h[3] << 16));
    reinterpret_cast<uint2*>(lo)[i] = make_uint2((uint32_t)l[0] | ((uint32_t)l[1] << 16),
                                                 (uint32_t)l[2] | ((uint32_t)l[3] << 16));
}

// ============================ fused HMMA machinery ============================
#define LDA 136
#define REG_B 34816
#define SM_A  0
#define SM_B  (2 * REG_B)
#define SM_T  (4 * REG_B)
#define SM_BI (6 * REG_B)
#define FUSED_SM (6 * REG_B + 1024)
#define GA_SM   (4 * REG_B + 1024)

__device__ __forceinline__ void load_tile_full(char* sm, int dst, const bf16* hi,
                                               const bf16* lo, int tid)
{
    const uint4* h4 = reinterpret_cast<const uint4*>(hi);
    const uint4* l4 = reinterpret_cast<const uint4*>(lo);
    #pragma unroll 4
    for (int q = 0; q < 8; q++) {
        int lin = q * 256 + tid;
        int row = lin >> 4, seg = lin & 15;
        *(uint4*)(sm + dst + row * 272 + seg * 16) = h4[lin];
        *(uint4*)(sm + dst + REG_B + row * 272 + seg * 16) = l4[lin];
    }
}
__device__ __forceinline__ void load_tile_bounded(char* sm, int dst, const bf16* hi,
                                                  const bf16* lo, int m0, int M, int tid)
{
    const uint4* h4 = reinterpret_cast<const uint4*>(hi);
    const uint4* l4 = reinterpret_cast<const uint4*>(lo);
    #pragma unroll 4
    for (int q = 0; q < 8; q++) {
        int lin = q * 256 + tid;
        int row = lin >> 4, seg = lin & 15;
        uint4 vh = make_uint4(0u,0u,0u,0u), vl = make_uint4(0u,0u,0u,0u);
        if (m0 + row < M) {
            size_t gi = (size_t)(m0 + row) * 16 + seg;
            vh = h4[gi]; vl = l4[gi];
        }
        *(uint4*)(sm + dst + row * 272 + seg * 16) = vh;
        *(uint4*)(sm + dst + REG_B + row * 272 + seg * 16) = vl;
    }
}

__device__ __forceinline__ void do_mma_stage(uint32_t smb, uint32_t aoff, uint32_t boff,
                                             int lane, int warp_m, int warp_n,
                                             float acc[2][8][4])
{
    #pragma unroll
    for (int mt = 0; mt < 2; mt++)
        #pragma unroll
        for (int nt = 0; nt < 8; nt++)
            #pragma unroll
            for (int r = 0; r < 4; r++) acc[mt][nt][r] = 0.f;

    const int a_row  = warp_m * 32 + (lane & 15);
    const int a_koff = (lane >> 4) << 3;
    const uint32_t sa_hi = smb + aoff + ((uint32_t)a_row * LDA + a_koff) * 2;
    const uint32_t sa_lo = sa_hi + REG_B;
    const int b_n    = warp_n * 64 + (lane & 7) + ((lane >> 4) << 3);
    const int b_koff = ((lane >> 3) & 1) << 3;
    const uint32_t sb_hi = smb + boff + ((uint32_t)b_n * LDA + b_koff) * 2;
    const uint32_t sb_lo = sb_hi + REG_B;

    #pragma unroll 2
    for (int kt = 0; kt < 8; kt++) {
        const uint32_t kb = kt * 32;
        uint32_t ah[2][4], al[2][4];
        ldsm_x4(ah[0], sa_hi + kb);
        ldsm_x4(ah[1], sa_hi + 16 * LDA * 2 + kb);
        ldsm_x4(al[0], sa_lo + kb);
        ldsm_x4(al[1], sa_lo + 16 * LDA * 2 + kb);
        uint32_t bh[4][4], bl[4][4];
        #pragma unroll
        for (int p = 0; p < 4; p++) {
            ldsm_x4(bh[p], sb_hi + (uint32_t)p * 16 * LDA * 2 + kb);
            ldsm_x4(bl[p], sb_lo + (uint32_t)p * 16 * LDA * 2 + kb);
        }
        #pragma unroll
        for (int mt = 0; mt < 2; mt++)
            #pragma unroll
            for (int p = 0; p < 4; p++)
                #pragma unroll
                for (int hf = 0; hf < 2; hf++) {
                    int nt = p * 2 + hf;
                    mma_bf16(acc[mt][nt], ah[mt], bh[p][hf*2], bh[p][hf*2+1]);
                    mma_bf16(acc[mt][nt], ah[mt], bl[p][hf*2], bl[p][hf*2+1]);
                    mma_bf16(acc[mt][nt], al[mt], bh[p][hf*2], bh[p][hf*2+1]);
                }
    }
}

template<bool BIAS>
__device__ __forceinline__ void store_T(char* sm, float acc[2][8][4], const float* sbias,
                                        int lane, int warp_m, int warp_n)
{
    #pragma unroll
    for (int mt = 0; mt < 2; mt++) {
        #pragma unroll
        for (int nt = 0; nt < 8; nt++) {
            int col = warp_n * 64 + nt * 8 + ((lane & 3) << 1);
            #pragma unroll
            for (int half = 0; half < 2; half++) {
                int r = warp_m * 32 + mt * 16 + (lane >> 2) + half * 8;
                float x0 = acc[mt][nt][half*2+0], x1 = acc[mt][nt][half*2+1];
                if (BIAS) { x0 += sbias[col]; x1 += sbias[col+1]; }
                x0 = x0 / (1.0f + expf(-x0));
                x1 = x1 / (1.0f + expf(-x1));
                bf16 h0, l0, h1, l1;
                split_bf16(x0, h0, l0); split_bf16(x1, h1, l1);
                uint32_t off = ((uint32_t)r * LDA + col) * 2;
                *(uint32_t*)(sm + SM_T + off) = (uint32_t)__bfloat16_as_ushort(h0)
                                              | ((uint32_t)__bfloat16_as_ushort(h1) << 16);
                *(uint32_t*)(sm + SM_T + REG_B + off) = (uint32_t)__bfloat16_as_ushort(l0)
                                              | ((uint32_t)__bfloat16_as_ushort(l1) << 16);
            }
        }
    }
}

template<bool BIAS>
__device__ __forceinline__ void store_out(float* out, float acc[2][8][4], const float* sbias,
                                          int m0, int M, int lane, int warp_m, int warp_n)
{
    #pragma unroll
    for (int mt = 0; mt < 2; mt++) {
        int r0 = m0 + warp_m * 32 + mt * 16 + (lane >> 2);
        #pragma unroll
        for (int nt = 0; nt < 8; nt++) {
            int col = warp_n * 64 + nt * 8 + ((lane & 3) << 1);
            float v[4];
            #pragma unroll
            for (int r = 0; r < 4; r++) {
                float x = acc[mt][nt][r];
                if (BIAS) x += sbias[col + (r & 1)];
                v[r] = x;
            }
            if (r0 < M)     *(float2*)&out[(size_t)r0 * NF + col]       = make_float2(v[0], v[1]);
            if (r0 + 8 < M) *(float2*)&out[(size_t)(r0 + 8) * NF + col] = make_float2(v[2], v[3]);
        }
    }
}

template<int NCH, bool BIAS>
__global__ void __launch_bounds__(256) fused_chain_k(
    const bf16* __restrict__ Ahi, const bf16* __restrict__ Alo,
    const bf16* __restrict__ W1hi, const bf16* __restrict__ W1lo,
    const bf16* __restrict__ W2hi, const bf16* __restrict__ W2lo,
    const bf16* __restrict__ W3hi, const bf16* __restrict__ W3lo,
    const bf16* __restrict__ W4hi, const bf16* __restrict__ W4lo,
    const float* __restrict__ bias1, const float* __restrict__ bias2,
    float* __restrict__ out1, float* __restrict__ out2, int M)
{
    extern __shared__ char sm[];
    const uint32_t smb = smem_u32(sm);
    const int tid  = threadIdx.x;
    const int lane = tid & 31;
    const int warp_m = (tid >> 5) >> 1;
    const int warp_n = (tid >> 5) & 1;
    const int m0   = blockIdx.x * 128;

    float* sb1 = (float*)(sm + SM_BI);
    float* sb2 = (float*)(sm + SM_BI + 512);
    if (BIAS && tid < 128) { sb1[tid] = bias1[tid]; sb2[tid] = bias2[tid]; }

    load_tile_bounded(sm, SM_A, Ahi, Alo, m0, M, tid);
    load_tile_full(sm, SM_B, W1hi, W1lo, tid);
    __syncthreads();

    float acc[2][8][4];
    do_mma_stage(smb, SM_A, SM_B, lane, warp_m, warp_n, acc);
    store_T<BIAS>(sm, acc, sb1, lane, warp_m, warp_n);
    __syncthreads();
    load_tile_full(sm, SM_B, W2hi, W2lo, tid);
    __syncthreads();
    do_mma_stage(smb, SM_T, SM_B, lane, warp_m, warp_n, acc);
    store_out<BIAS>(out1, acc, sb2, m0, M, lane, warp_m, warp_n);

    if (NCH == 2) {
        __syncthreads();
        load_tile_full(sm, SM_B, W3hi, W3lo, tid);
        __syncthreads();
        do_mma_stage(smb, SM_A, SM_B, lane, warp_m, warp_n, acc);
        store_T<false>(sm, acc, sb1, lane, warp_m, warp_n);
        __syncthreads();
        load_tile_full(sm, SM_B, W4hi, W4lo, tid);
        __syncthreads();
        do_mma_stage(smb, SM_T, SM_B, lane, warp_m, warp_n, acc);
        store_out<false>(out2, acc, sb2, m0, M, lane, warp_m, warp_n);
    }
}

// ---------------- g = force@euW fused with atom += sum_d force*g ----------------
__global__ void __launch_bounds__(256) gemm_atom_k(
    const bf16* __restrict__ Fhi, const bf16* __restrict__ Flo,
    const bf16* __restrict__ Whi, const bf16* __restrict__ Wlo,
    const float* __restrict__ force, float* __restrict__ atom, int M)
{
    extern __shared__ char sm[];
    const uint32_t smb = smem_u32(sm);
    const int tid  = threadIdx.x;
    const int lane = tid & 31;
    const int warp_m = (tid >> 5) >> 1;
    const int warp_n = (tid >> 5) & 1;
    const int m0   = blockIdx.x * 128;

    load_tile_bounded(sm, SM_A, Fhi, Flo, m0, M, tid);
    load_tile_full(sm, SM_B, Whi, Wlo, tid);
    __syncthreads();

    float acc[2][8][4];
    do_mma_stage(smb, SM_A, SM_B, lane, warp_m, warp_n, acc);

    #pragma unroll
    for (int mt = 0; mt < 2; mt++) {
        #pragma unroll
        for (int half = 0; half < 2; half++) {
            int r = m0 + warp_m * 32 + mt * 16 + (lane >> 2) + half * 8;
            if (r >= M) continue;
            int n = r / 3;
            #pragma unroll
            for (int nt = 0; nt < 8; nt++) {
                int col = warp_n * 64 + nt * 8 + ((lane & 3) << 1);
                float2 f = *(const float2*)&force[(size_t)r * NF + col];
                atomicAdd(&atom[(size_t)n * NF + col],     acc[mt][nt][half*2+0] * f.x);
                atomicAdd(&atom[(size_t)n * NF + col + 1], acc[mt][nt][half*2+1] * f.y);
            }
        }
    }
}

// ---------------- init: atom = node_emb[z] ----------------
__global__ void init_atom_k(const int* __restrict__ z, const float* __restrict__ emb,
                            float* __restrict__ atom)
{
    int idx = blockIdx.x * blockDim.x + threadIdx.x;
    int n = idx >> 7, f = idx & 127;
    atom[idx] = emb[(size_t)z[n] * NF + f];
}

// ---------------- edge embedding (sorted order) ----------------
__global__ void edge_embed_k(const float* __restrict__ pos, const int* __restrict__ si,
                             const int* __restrict__ sj,
                             float* __restrict__ dist, float* __restrict__ dir)
{
    int e = blockIdx.x * blockDim.x + threadIdx.x;
    if (e >= N_EDGES) return;
    int i = si[e], j = sj[e];
    float dx = pos[j*3+0] - pos[i*3+0];
    float dy = pos[j*3+1] - pos[i*3+1];
    float dz = pos[j*3+2] - pos[i*3+2];
    float d = sqrtf(dx*dx + dy*dy + dz*dz + 1e-12f);
    float inv = 1.0f / d;
    dir[e*3+0] = dx*inv; dir[e*3+1] = dy*inv; dir[e*3+2] = dz*inv;
    float fc = (d < CUTOFF_R) ? 0.5f * (cosf(3.14159265358979323846f * d / CUTOFF_R) + 1.0f) : 0.0f;
    const float inv_w = 1.0f / (CUTOFF_R / NB);
    #pragma unroll
    for (int b = 0; b < NB; b++) {
        float c = CUTOFF_R * (float)b / (float)(NB - 1);
        float t = (d - c) * inv_w;
        dist[(size_t)e*NB + b] = expf(-t*t) * fc;
    }
}

// ---------------- msg per-node: no atomics ----------------
__global__ void __launch_bounds__(128) msg_node_k(
    const float* __restrict__ h, const float* __restrict__ dist,
    const int* __restrict__ rptr, const int* __restrict__ sj,
    const float* __restrict__ meW,
    bf16* __restrict__ mhi, bf16* __restrict__ mlo, float* __restrict__ atom)
{
    __shared__ float sW[NB * NF];
    const int f = threadIdx.x;
    #pragma unroll
    for (int b = 0; b < NB; b++) sW[b*NF + f] = meW[b*NF + f];
    __syncthreads();
    const int n0 = blockIdx.x * 8;
    for (int q = 0; q < 8; q++) {
        int n = n0 + q;
        float hn = h[(size_t)n * NF + f];
        float acc = 0.f;
        int e0 = rptr[n], e1 = rptr[n+1];
        for (int e = e0; e < e1; e++) {
            float me = 0.f;
            #pragma unroll
            for (int b = 0; b < NB; b++)
                me = fmaf(dist[(size_t)e*NB + b], sW[b*NF + f], me);
            float hj = h[(size_t)sj[e] * NF + f];
            float m = me * hn * hj;
            bf16 hb, lb; split_bf16(m, hb, lb);
            mhi[(size_t)e*NF + f] = hb;
            mlo[(size_t)e*NF + f] = lb;
            acc += m;
        }
        atom[(size_t)n * NF + f] += acc;
    }
}

// ---------------- force per-node gather: Fnew = Fold + segsum, + hi/lo ----------------
__global__ void __launch_bounds__(128) force_node_k(
    const float* __restrict__ p1, const float* __restrict__ p2,
    const float* __restrict__ dir, const float* __restrict__ Fold,
    const int* __restrict__ rptr, const int* __restrict__ sj,
    float* __restrict__ Fnew, bf16* __restrict__ fhi, bf16* __restrict__ flo)
{
    const int f = threadIdx.x;
    const int n0 = blockIdx.x * 4;
    for (int q = 0; q < 4; q++) {
        int n = n0 + q;
        float fd0 = 0.f, fd1 = 0.f, fd2 = 0.f;
        int e0 = rptr[n], e1 = rptr[n+1];
        for (int e = e0; e < e1; e++) {
            float v1 = p1[(size_t)e*NF + f];
            float v2 = p2[(size_t)e*NF + f];
            float dx = dir[e*3+0], dy = dir[e*3+1], dz = dir[e*3+2];
            const float* fj = &Fold[(size_t)sj[e] * 3 * NF];
            fd0 = fmaf(v1, dx, fmaf(v2, fj[f],        fd0));
            fd1 = fmaf(v1, dy, fmaf(v2, fj[NF + f],   fd1));
            fd2 = fmaf(v1, dz, fmaf(v2, fj[2*NF + f], fd2));
        }
        size_t base = (size_t)n * 3 * NF + f;
        float o0 = Fold[base]        + fd0;
        float o1 = Fold[base + NF]   + fd1;
        float o2 = Fold[base + 2*NF] + fd2;
        Fnew[base]        = o0;
        Fnew[base + NF]   = o1;
        Fnew[base + 2*NF] = o2;
        bf16 hb, lb;
        split_bf16(o0, hb, lb); fhi[base] = hb;        flo[base] = lb;
        split_bf16(o1, hb, lb); fhi[base + NF] = hb;   flo[base + NF] = lb;
        split_bf16(o2, hb, lb); fhi[base + 2*NF] = hb; flo[base + 2*NF] = lb;
    }
}

// ---------------- host ----------------
extern "C" void kernel_launch(void* const* d_in, const int* in_sizes, int n_in,
                              void* d_out, int out_size)
{
    const int*   z        = (const int*)  d_in[0];
    const float* pos      = (const float*)d_in[1];
    const int*   ei       = (const int*)  d_in[4];
    const float* node_emb = (const float*)d_in[5];
    const float* mnp_W1   = (const float*)d_in[6];
    const float* mnp_b1   = (const float*)d_in[7];
    const float* mnp_W2   = (const float*)d_in[8];
    const float* mnp_b2   = (const float*)d_in[9];
    const float* me_W     = (const float*)d_in[10];
    const float* em1_W1   = (const float*)d_in[11];
    const float* em1_W2   = (const float*)d_in[12];
    const float* em2_W1   = (const float*)d_in[13];
    const float* em2_W2   = (const float*)d_in[14];
    const float* eu_W     = (const float*)d_in[15];

    float* atom = (float*)d_out;

    float *dist, *dir, *h, *p1, *p2, *forceA, *force_fb;
    bf16 *bhi1, *blo1, *bhi2, *blo2, *whi, *wlo;
    int *cnt, *off, *rptr, *si, *sj;
    cudaGetSymbolAddress((void**)&dist,     g_dist);
    cudaGetSymbolAddress((void**)&dir,      g_dir);
    cudaGetSymbolAddress((void**)&h,        g_h);
    cudaGetSymbolAddress((void**)&p1,       g_p1);
    cudaGetSymbolAddress((void**)&p2,       g_p2);
    cudaGetSymbolAddress((void**)&forceA,   g_forceA);
    cudaGetSymbolAddress((void**)&force_fb, g_force_fb);
    cudaGetSymbolAddress((void**)&bhi1, g_bhi1);
    cudaGetSymbolAddress((void**)&blo1, g_blo1);
    cudaGetSymbolAddress((void**)&bhi2, g_bhi2);
    cudaGetSymbolAddress((void**)&blo2, g_blo2);
    cudaGetSymbolAddress((void**)&whi,  g_whi);
    cudaGetSymbolAddress((void**)&wlo,  g_wlo);
    cudaGetSymbolAddress((void**)&cnt,  g_cnt);
    cudaGetSymbolAddress((void**)&off,  g_off);
    cudaGetSymbolAddress((void**)&rptr, g_rptr);
    cudaGetSymbolAddress((void**)&si,   g_si);
    cudaGetSymbolAddress((void**)&sj,   g_sj);

    float* forceB;
    if (out_size >= N_NODES * (NF + 3 * NF)) forceB = atom + (size_t)N_NODES * NF;
    else                                     forceB = force_fb;

    cudaFuncSetAttribute(fused_chain_k<1, true >, cudaFuncAttributeMaxDynamicSharedMemorySize, FUSED_SM);
    cudaFuncSetAttribute(fused_chain_k<2, false>, cudaFuncAttributeMaxDynamicSharedMemorySize, FUSED_SM);
    cudaFuncSetAttribute(gemm_atom_k, cudaFuncAttributeMaxDynamicSharedMemorySize, GA_SM);
    cudaFuncSetAttribute(prep_all_k, cudaFuncAttributeMaxDynamicSharedMemorySize, PREP_SM);

    // ---- CSR build ----
    cudaMemsetAsync(cnt, 0, N_NODES * sizeof(int), 0);
    cudaMemsetAsync(off, 0, N_NODES * sizeof(int), 0);
    count_k<<<(N_EDGES + 255) / 256, 256>>>(ei, cnt);
    scan_k<<<1, 1024>>>(cnt, rptr);
    place_k<<<(N_EDGES + 255) / 256, 256>>>(ei, rptr, off, si, sj);

    prep_all_k<<<21, 256, PREP_SM>>>(mnp_W1, mnp_W2, em1_W1, em1_W2, em2_W1, em2_W2, eu_W,
                                     whi, wlo);

    cudaMemsetAsync(forceA, 0, (size_t)N_NODES * 3 * NF * sizeof(float), 0);

    init_atom_k<<<(N_NODES * NF) / 256, 256>>>(z, node_emb, atom);
    edge_embed_k<<<(N_EDGES + 255) / 256, 256>>>(pos, si, sj, dist, dir);

    const int GN  = (N_NODES + 127) / 128;       // 79
    const int GE  = N_EDGES / 128;               // 1250
    const int GF3 = (N_NODES * 3 + 127) / 128;   // 235

    for (int l = 0; l < NLAYERS; l++) {
        const bf16* Whi = whi + (size_t)l * 7 * 16384;
        const bf16* Wlo = wlo + (size_t)l * 7 * 16384;
        const float* b1 = mnp_b1 + (size_t)l * NF;
        const float* b2 = mnp_b2 + (size_t)l * NF;
        const float* mW = me_W   + (size_t)l * NB * NF;

        float* Fold = (l % 2 == 0) ? forceA : forceB;
        float* Fnew = (l % 2 == 0) ? forceB : forceA;

        // atom -> hi/lo
        conv_k<<<(N_NODES * NF / 4 + 255) / 256, 256>>>(atom, bhi1, blo1, N_NODES * NF / 4);

        // h = silu(atom@W1+b1)@W2+b2
        fused_chain_k<1, true><<<GN, 256, FUSED_SM>>>(
            bhi1, blo1,
            Whi + 0*16384, Wlo + 0*16384, Whi + 1*16384, Wlo + 1*16384,
            nullptr, nullptr, nullptr, nullptr,
            b1, b2, h, nullptr, N_NODES);

        // msg (sorted, hi/lo) + atom segsum (no atomics)
        msg_node_k<<<N_NODES / 8, NF>>>(h, dist, rptr, sj, mW, bhi1, blo1, atom);

        // p1 = silu(msg@e11)@e12 ; p2 = silu(msg@e21)@e22
        fused_chain_k<2, false><<<GE, 256, FUSED_SM>>>(
            bhi1, blo1,
            Whi + 2*16384, Wlo + 2*16384, Whi + 3*16384, Wlo + 3*16384,
            Whi + 4*16384, Wlo + 4*16384, Whi + 5*16384, Wlo + 5*16384,
            nullptr, nullptr, p1, p2, N_EDGES);

        // force gather-update (no atomics, no fdelta), emits hi/lo
        force_node_k<<<N_NODES / 4, NF>>>(p1, p2, dir, Fold, rptr, sj, Fnew, bhi2, blo2);

        // atom += sum_d Fnew * (Fnew@euW)
        gemm_atom_k<<<GF3, 256, GA_SM>>>(bhi2, blo2, Whi + 6*16384, Wlo + 6*16384,
                                         Fnew, atom, N_NODES * 3);
    }
}

// round 15
// speedup vs baseline: 1.0512x; 1.0512x over previous
#include <cuda_runtime.h>
#include <cuda_bf16.h>
#include <math.h>
#include <stdint.h>

#define N_NODES 10000
#define N_EDGES 160000
#define NF 128
#define NB 20
#define NLAYERS 3
#define CUTOFF_R 5.0f

typedef __nv_bfloat16 bf16;

// ---------------- device scratch ----------------
__device__ float g_dist[(size_t)N_EDGES * NB];
__device__ float g_dir[(size_t)N_EDGES * 3];
__device__ float g_h[(size_t)N_NODES * NF];
__device__ float g_fdelta[(size_t)N_NODES * 3 * NF];
__device__ float g_force_fb[(size_t)N_NODES * 3 * NF];
__device__ bf16 g_bhi1[(size_t)N_EDGES * NF];       // atom / msg hi
__device__ bf16 g_blo1[(size_t)N_EDGES * NF];
__device__ bf16 g_bhi2[(size_t)N_NODES * 3 * NF];   // silu intermediate (nodes) / force hi
__device__ bf16 g_blo2[(size_t)N_NODES * 3 * NF];
__device__ bf16 g_whi[21 * 16384];
__device__ bf16 g_wlo[21 * 16384];

// ============================ helpers ============================
__device__ __forceinline__ uint32_t smem_u32(const void* p) {
    uint32_t a;
    asm("{ .reg .u64 t; cvta.to.shared.u64 t, %1; cvt.u32.u64 %0, t; }" : "=r"(a) : "l"(p));
    return a;
}
__device__ __forceinline__ void ldsm_x4(uint32_t* r, uint32_t addr) {
    asm volatile("ldmatrix.sync.aligned.m8n8.x4.shared.b16 {%0,%1,%2,%3}, [%4];"
                 : "=r"(r[0]), "=r"(r[1]), "=r"(r[2]), "=r"(r[3]) : "r"(addr));
}
__device__ __forceinline__ void mma_bf16(float* d, const uint32_t* a, uint32_t b0, uint32_t b1) {
    asm volatile(
        "mma.sync.aligned.m16n8k16.row.col.f32.bf16.bf16.f32 "
        "{%0,%1,%2,%3},{%4,%5,%6,%7},{%8,%9},{%0,%1,%2,%3};"
        : "+f"(d[0]), "+f"(d[1]), "+f"(d[2]), "+f"(d[3])
        : "r"(a[0]), "r"(a[1]), "r"(a[2]), "r"(a[3]), "r"(b0), "r"(b1));
}
__device__ __forceinline__ void split_bf16(float v, bf16& h, bf16& l) {
    h = __float2bfloat16(v);
    l = __float2bfloat16(v - __bfloat162float(h));
}

// ---------------- weight prep (all 21 matrices, one launch) ----------------
#define PREP_SM (2 * 128 * 136 * 2)
__global__ void prep_all_k(const float* __restrict__ W1, const float* __restrict__ W2,
                           const float* __restrict__ W3, const float* __restrict__ W4,
                           const float* __restrict__ W5, const float* __restrict__ W6,
                           const float* __restrict__ W7,
                           bf16* __restrict__ dhi, bf16* __restrict__ dlo)
{
    extern __shared__ char sm[];
    bf16* shi = (bf16*)sm;
    bf16* slo = (bf16*)(sm + 128 * 136 * 2);
    const int tid = threadIdx.x;
    const int fam = blockIdx.x / 3;
    const int lyr = blockIdx.x % 3;
    const float* srcs[7] = {W1, W2, W3, W4, W5, W6, W7};
    const float4* s4 = reinterpret_cast<const float4*>(srcs[fam] + (size_t)lyr * 16384);
    #pragma unroll 4
    for (int q = 0; q < 16; q++) {
        int lin = q * 256 + tid;
        int k = lin >> 5, n4 = (lin & 31) << 2;
        float4 v = s4[lin];
        float vv[4] = {v.x, v.y, v.z, v.w};
        #pragma unroll
        for (int t = 0; t < 4; t++) {
            bf16 hb, lb; split_bf16(vv[t], hb, lb);
            shi[(n4 + t) * 136 + k] = hb;
            slo[(n4 + t) * 136 + k] = lb;
        }
    }
    __syncthreads();
    size_t dslot = (size_t)(lyr * 7 + fam) * 16384;
    uint4* dh4 = reinterpret_cast<uint4*>(dhi + dslot);
    uint4* dl4 = reinterpret_cast<uint4*>(dlo + dslot);
    const char* smc = sm;
    #pragma unroll 4
    for (int q = 0; q < 8; q++) {
        int lin = q * 256 + tid;
        int row = lin >> 4, seg = lin & 15;
        dh4[lin] = *(const uint4*)(smc + row * 272 + seg * 16);
        dl4[lin] = *(const uint4*)(smc + 128 * 136 * 2 + row * 272 + seg * 16);
    }
}

// ---------------- fp32 -> bf16 hi/lo ----------------
__global__ void conv_k(const float* __restrict__ x, bf16* __restrict__ hi,
                       bf16* __restrict__ lo, int n4)
{
    int i = blockIdx.x * blockDim.x + threadIdx.x;
    if (i >= n4) return;
    float4 v = reinterpret_cast<const float4*>(x)[i];
    float vv[4] = {v.x, v.y, v.z, v.w};
    uint16_t h[4], l[4];
    #pragma unroll
    for (int t = 0; t < 4; t++) {
        bf16 hb, lb; split_bf16(vv[t], hb, lb);
        h[t] = __bfloat16_as_ushort(hb); l[t] = __bfloat16_as_ushort(lb);
    }
    reinterpret_cast<uint2*>(hi)[i] = make_uint2((uint32_t)h[0] | ((uint32_t)h[1] << 16),
                                                 (uint32_t)h[2] | ((uint32_t)h[3] << 16));
    reinterpret_cast<uint2*>(lo)[i] = make_uint2((uint32_t)l[0] | ((uint32_t)l[1] << 16),
                                                 (uint32_t)l[2] | ((uint32_t)l[3] << 16));
}

// ============================ fused HMMA machinery ============================
#define LDA 136
#define REG_B 34816
#define SM_A  0
#define SM_B  (2 * REG_B)
#define SM_T  (4 * REG_B)
#define SM_BI (6 * REG_B)
#define FUSED_SM (6 * REG_B + 1024)
#define GA_SM   (4 * REG_B + 1024)

__device__ __forceinline__ void load_tile_full(char* sm, int dst, const bf16* hi,
                                               const bf16* lo, int tid)
{
    const uint4* h4 = reinterpret_cast<const uint4*>(hi);
    const uint4* l4 = reinterpret_cast<const uint4*>(lo);
    #pragma unroll 4
    for (int q = 0; q < 8; q++) {
        int lin = q * 256 + tid;
        int row = lin >> 4, seg = lin & 15;
        *(uint4*)(sm + dst + row * 272 + seg * 16) = h4[lin];
        *(uint4*)(sm + dst + REG_B + row * 272 + seg * 16) = l4[lin];
    }
}
__device__ __forceinline__ void load_tile_bounded(char* sm, int dst, const bf16* hi,
                                                  const bf16* lo, int m0, int M, int tid)
{
    const uint4* h4 = reinterpret_cast<const uint4*>(hi);
    const uint4* l4 = reinterpret_cast<const uint4*>(lo);
    #pragma unroll 4
    for (int q = 0; q < 8; q++) {
        int lin = q * 256 + tid;
        int row = lin >> 4, seg = lin & 15;
        uint4 vh = make_uint4(0u,0u,0u,0u), vl = make_uint4(0u,0u,0u,0u);
        if (m0 + row < M) {
            size_t gi = (size_t)(m0 + row) * 16 + seg;
            vh = h4[gi]; vl = l4[gi];
        }
        *(uint4*)(sm + dst + row * 272 + seg * 16) = vh;
        *(uint4*)(sm + dst + REG_B + row * 272 + seg * 16) = vl;
    }
}

__device__ __forceinline__ void do_mma_stage(uint32_t smb, uint32_t aoff, uint32_t boff,
                                             int lane, int warp_m, int warp_n,
                                             float acc[2][8][4])
{
    #pragma unroll
    for (int mt = 0; mt < 2; mt++)
        #pragma unroll
        for (int nt = 0; nt < 8; nt++)
            #pragma unroll
            for (int r = 0; r < 4; r++) acc[mt][nt][r] = 0.f;

    const int a_row  = warp_m * 32 + (lane & 15);
    const int a_koff = (lane >> 4) << 3;
    const uint32_t sa_hi = smb + aoff + ((uint32_t)a_row * LDA + a_koff) * 2;
    const uint32_t sa_lo = sa_hi + REG_B;
    const int b_n    = warp_n * 64 + (lane & 7) + ((lane >> 4) << 3);
    const int b_koff = ((lane >> 3) & 1) << 3;
    const uint32_t sb_hi = smb + boff + ((uint32_t)b_n * LDA + b_koff) * 2;
    const uint32_t sb_lo = sb_hi + REG_B;

    #pragma unroll 2
    for (int kt = 0; kt < 8; kt++) {
        const uint32_t kb = kt * 32;
        uint32_t ah[2][4], al[2][4];
        ldsm_x4(ah[0], sa_hi + kb);
        ldsm_x4(ah[1], sa_hi + 16 * LDA * 2 + kb);
        ldsm_x4(al[0], sa_lo + kb);
        ldsm_x4(al[1], sa_lo + 16 * LDA * 2 + kb);
        uint32_t bh[4][4], bl[4][4];
        #pragma unroll
        for (int p = 0; p < 4; p++) {
            ldsm_x4(bh[p], sb_hi + (uint32_t)p * 16 * LDA * 2 + kb);
            ldsm_x4(bl[p], sb_lo + (uint32_t)p * 16 * LDA * 2 + kb);
        }
        #pragma unroll
        for (int mt = 0; mt < 2; mt++)
            #pragma unroll
            for (int p = 0; p < 4; p++)
                #pragma unroll
                for (int hf = 0; hf < 2; hf++) {
                    int nt = p * 2 + hf;
                    mma_bf16(acc[mt][nt], ah[mt], bh[p][hf*2], bh[p][hf*2+1]);
                    mma_bf16(acc[mt][nt], ah[mt], bl[p][hf*2], bl[p][hf*2+1]);
                    mma_bf16(acc[mt][nt], al[mt], bh[p][hf*2], bh[p][hf*2+1]);
                }
    }
}

template<bool BIAS>
__device__ __forceinline__ void store_T(char* sm, float acc[2][8][4], const float* sbias,
                                        int lane, int warp_m, int warp_n)
{
    #pragma unroll
    for (int mt = 0; mt < 2; mt++) {
        #pragma unroll
        for (int nt = 0; nt < 8; nt++) {
            int col = warp_n * 64 + nt * 8 + ((lane & 3) << 1);
            #pragma unroll
            for (int half = 0; half < 2; half++) {
                int r = warp_m * 32 + mt * 16 + (lane >> 2) + half * 8;
                float x0 = acc[mt][nt][half*2+0], x1 = acc[mt][nt][half*2+1];
                if (BIAS) { x0 += sbias[col]; x1 += sbias[col+1]; }
                x0 = x0 / (1.0f + expf(-x0));
                x1 = x1 / (1.0f + expf(-x1));
                bf16 h0, l0, h1, l1;
                split_bf16(x0, h0, l0); split_bf16(x1, h1, l1);
                uint32_t off = ((uint32_t)r * LDA + col) * 2;
                *(uint32_t*)(sm + SM_T + off) = (uint32_t)__bfloat16_as_ushort(h0)
                                              | ((uint32_t)__bfloat16_as_ushort(h1) << 16);
                *(uint32_t*)(sm + SM_T + REG_B + off) = (uint32_t)__bfloat16_as_ushort(l0)
                                              | ((uint32_t)__bfloat16_as_ushort(l1) << 16);
            }
        }
    }
}

template<bool BIAS>
__device__ __forceinline__ void store_out(float* out, float acc[2][8][4], const float* sbias,
                                          int m0, int M, int lane, int warp_m, int warp_n)
{
    #pragma unroll
    for (int mt = 0; mt < 2; mt++) {
        int r0 = m0 + warp_m * 32 + mt * 16 + (lane >> 2);
        #pragma unroll
        for (int nt = 0; nt < 8; nt++) {
            int col = warp_n * 64 + nt * 8 + ((lane & 3) << 1);
            float v[4];
            #pragma unroll
            for (int r = 0; r < 4; r++) {
                float x = acc[mt][nt][r];
                if (BIAS) x += sbias[col + (r & 1)];
                v[r] = x;
            }
            if (r0 < M)     *(float2*)&out[(size_t)r0 * NF + col]       = make_float2(v[0], v[1]);
            if (r0 + 8 < M) *(float2*)&out[(size_t)(r0 + 8) * NF + col] = make_float2(v[2], v[3]);
        }
    }
}

// ---------------- node chain: h = silu(A@W1+b1)@W2+b2 ----------------
__global__ void __launch_bounds__(256) fused_chain1_k(
    const bf16* __restrict__ Ahi, const bf16* __restrict__ Alo,
    const bf16* __restrict__ W1hi, const bf16* __restrict__ W1lo,
    const bf16* __restrict__ W2hi, const bf16* __restrict__ W2lo,
    const float* __restrict__ bias1, const float* __restrict__ bias2,
    float* __restrict__ out1, int M)
{
    extern __shared__ char sm[];
    const uint32_t smb = smem_u32(sm);
    const int tid  = threadIdx.x;
    const int lane = tid & 31;
    const int warp_m = (tid >> 5) >> 1;
    const int warp_n = (tid >> 5) & 1;
    const int m0   = blockIdx.x * 128;

    float* sb1 = (float*)(sm + SM_BI);
    float* sb2 = (float*)(sm + SM_BI + 512);
    if (tid < 128) { sb1[tid] = bias1[tid]; sb2[tid] = bias2[tid]; }

    load_tile_bounded(sm, SM_A, Ahi, Alo, m0, M, tid);
    load_tile_full(sm, SM_B, W1hi, W1lo, tid);
    __syncthreads();

    float acc[2][8][4];
    do_mma_stage(smb, SM_A, SM_B, lane, warp_m, warp_n, acc);
    store_T<true>(sm, acc, sb1, lane, warp_m, warp_n);
    __syncthreads();
    load_tile_full(sm, SM_B, W2hi, W2lo, tid);
    __syncthreads();
    do_mma_stage(smb, SM_T, SM_B, lane, warp_m, warp_n, acc);
    store_out<true>(out1, acc, sb2, m0, M, lane, warp_m, warp_n);
}

// ---------------- edge chain + fused scatter ----------------
// p1 = silu(msg@W1)@W2 (kept in regs), p2 = silu(msg@W3)@W4,
// then fdelta[i] += p1*dir + p2*force[j]  (no p1/p2 gmem round-trip).
__global__ void __launch_bounds__(256) chain2_scatter_k(
    const bf16* __restrict__ Ahi, const bf16* __restrict__ Alo,
    const bf16* __restrict__ W1hi, const bf16* __restrict__ W1lo,
    const bf16* __restrict__ W2hi, const bf16* __restrict__ W2lo,
    const bf16* __restrict__ W3hi, const bf16* __restrict__ W3lo,
    const bf16* __restrict__ W4hi, const bf16* __restrict__ W4lo,
    const int* __restrict__ ei, const float* __restrict__ dir,
    const float* __restrict__ force, float* __restrict__ fdelta)
{
    extern __shared__ char sm[];
    const uint32_t smb = smem_u32(sm);
    const int tid  = threadIdx.x;
    const int lane = tid & 31;
    const int warp_m = (tid >> 5) >> 1;
    const int warp_n = (tid >> 5) & 1;
    const int m0   = blockIdx.x * 128;      // E % 128 == 0

    load_tile_full(sm, SM_A, Ahi + (size_t)m0 * NF, Alo + (size_t)m0 * NF, tid);
    load_tile_full(sm, SM_B, W1hi, W1lo, tid);
    __syncthreads();

    float acc[2][8][4];
    // stage 1-2 -> p1 (stashed in registers)
    do_mma_stage(smb, SM_A, SM_B, lane, warp_m, warp_n, acc);
    store_T<false>(sm, acc, nullptr, lane, warp_m, warp_n);
    __syncthreads();
    load_tile_full(sm, SM_B, W2hi, W2lo, tid);
    __syncthreads();
    do_mma_stage(smb, SM_T, SM_B, lane, warp_m, warp_n, acc);

    float p1r[2][8][4];
    #pragma unroll
    for (int mt = 0; mt < 2; mt++)
        #pragma unroll
        for (int nt = 0; nt < 8; nt++)
            #pragma unroll
            for (int r = 0; r < 4; r++) p1r[mt][nt][r] = acc[mt][nt][r];

    // stage 3-4 -> p2 (in acc)
    __syncthreads();
    load_tile_full(sm, SM_B, W3hi, W3lo, tid);
    __syncthreads();
    do_mma_stage(smb, SM_A, SM_B, lane, warp_m, warp_n, acc);
    store_T<false>(sm, acc, nullptr, lane, warp_m, warp_n);
    __syncthreads();
    load_tile_full(sm, SM_B, W4hi, W4lo, tid);
    __syncthreads();
    do_mma_stage(smb, SM_T, SM_B, lane, warp_m, warp_n, acc);

    // fused scatter epilogue
    #pragma unroll
    for (int mt = 0; mt < 2; mt++) {
        #pragma unroll
        for (int half = 0; half < 2; half++) {
            int e = m0 + warp_m * 32 + mt * 16 + (lane >> 2) + half * 8;
            int i = ei[e], j = ei[N_EDGES + e];
            float ddir[3];
            ddir[0] = dir[e*3+0]; ddir[1] = dir[e*3+1]; ddir[2] = dir[e*3+2];
            const float* fj = &force[(size_t)j * 3 * NF];
            float* fd = &fdelta[(size_t)i * 3 * NF];
            #pragma unroll
            for (int nt = 0; nt < 8; nt++) {
                int col = warp_n * 64 + nt * 8 + ((lane & 3) << 1);
                float v1a = p1r[mt][nt][half*2+0], v1b = p1r[mt][nt][half*2+1];
                float v2a = acc[mt][nt][half*2+0], v2b = acc[mt][nt][half*2+1];
                #pragma unroll
                for (int d = 0; d < 3; d++) {
                    float2 f = *(const float2*)&fj[d*NF + col];
                    atomicAdd(&fd[d*NF + col],     fmaf(v1a, ddir[d], v2a * f.x));
                    atomicAdd(&fd[d*NF + col + 1], fmaf(v1b, ddir[d], v2b * f.y));
                }
            }
        }
    }
}

// ---------------- g = force@euW fused with atom += sum_d force*g ----------------
__global__ void __launch_bounds__(256) gemm_atom_k(
    const bf16* __restrict__ Fhi, const bf16* __restrict__ Flo,
    const bf16* __restrict__ Whi, const bf16* __restrict__ Wlo,
    const float* __restrict__ force, float* __restrict__ atom, int M)
{
    extern __shared__ char sm[];
    const uint32_t smb = smem_u32(sm);
    const int tid  = threadIdx.x;
    const int lane = tid & 31;
    const int warp_m = (tid >> 5) >> 1;
    const int warp_n = (tid >> 5) & 1;
    const int m0   = blockIdx.x * 128;

    load_tile_bounded(sm, SM_A, Fhi, Flo, m0, M, tid);
    load_tile_full(sm, SM_B, Whi, Wlo, tid);
    __syncthreads();

    float acc[2][8][4];
    do_mma_stage(smb, SM_A, SM_B, lane, warp_m, warp_n, acc);

    #pragma unroll
    for (int mt = 0; mt < 2; mt++) {
        #pragma unroll
        for (int half = 0; half < 2; half++) {
            int r = m0 + warp_m * 32 + mt * 16 + (lane >> 2) + half * 8;
            if (r >= M) continue;
            int n = r / 3;
            #pragma unroll
            for (int nt = 0; nt < 8; nt++) {
                int col = warp_n * 64 + nt * 8 + ((lane & 3) << 1);
                float2 f = *(const float2*)&force[(size_t)r * NF + col];
                atomicAdd(&atom[(size_t)n * NF + col],     acc[mt][nt][half*2+0] * f.x);
                atomicAdd(&atom[(size_t)n * NF + col + 1], acc[mt][nt][half*2+1] * f.y);
            }
        }
    }
}

// ---------------- init: atom = node_emb[z] ----------------
__global__ void init_atom_k(const int* __restrict__ z, const float* __restrict__ emb,
                            float* __restrict__ atom)
{
    int idx = blockIdx.x * blockDim.x + threadIdx.x;
    int n = idx >> 7, f = idx & 127;
    atom[idx] = emb[(size_t)z[n] * NF + f];
}

// ---------------- edge embedding ----------------
__global__ void edge_embed_k(const float* __restrict__ pos, const int* __restrict__ ei,
                             float* __restrict__ dist, float* __restrict__ dir)
{
    int e = blockIdx.x * blockDim.x + threadIdx.x;
    if (e >= N_EDGES) return;
    int i = ei[e], j = ei[N_EDGES + e];
    float dx = pos[j*3+0] - pos[i*3+0];
    float dy = pos[j*3+1] - pos[i*3+1];
    float dz = pos[j*3+2] - pos[i*3+2];
    float d = sqrtf(dx*dx + dy*dy + dz*dz + 1e-12f);
    float inv = 1.0f / d;
    dir[e*3+0] = dx*inv; dir[e*3+1] = dy*inv; dir[e*3+2] = dz*inv;
    float fc = (d < CUTOFF_R) ? 0.5f * (cosf(3.14159265358979323846f * d / CUTOFF_R) + 1.0f) : 0.0f;
    const float inv_w = 1.0f / (CUTOFF_R / NB);
    #pragma unroll
    for (int b = 0; b < NB; b++) {
        float c = CUTOFF_R * (float)b / (float)(NB - 1);
        float t = (d - c) * inv_w;
        dist[(size_t)e*NB + b] = expf(-t*t) * fc;
    }
}

// ---------------- msg = (dist@meW)*h[i]*h[j] -> hi/lo; atom += segsum ----------------
__global__ void msg_k2(const float* __restrict__ h, const float* __restrict__ dist,
                       const int* __restrict__ ei, const float* __restrict__ meW,
                       bf16* __restrict__ mhi, bf16* __restrict__ mlo,
                       float* __restrict__ atom)
{
    __shared__ float sW[NB * NF];
    __shared__ float sd[32 * NB];
    int f = threadIdx.x;
    #pragma unroll
    for (int b = 0; b < NB; b++) sW[b*NF + f] = meW[b*NF + f];
    int e0 = blockIdx.x * 32;
    for (int q = f; q < 32 * NB; q += NF) sd[q] = dist[(size_t)e0 * NB + q];
    __syncthreads();
    #pragma unroll 2
    for (int t = 0; t < 32; t++) {
        int e = e0 + t;
        int i = ei[e], j = ei[N_EDGES + e];
        float me = 0.f;
        #pragma unroll
        for (int b = 0; b < NB; b++) me = fmaf(sd[t*NB + b], sW[b*NF + f], me);
        float m = me * h[(size_t)i*NF + f] * h[(size_t)j*NF + f];
        bf16 hb, lb; split_bf16(m, hb, lb);
        mhi[(size_t)e*NF + f] = hb;
        mlo[(size_t)e*NF + f] = lb;
        atomicAdd(&atom[(size_t)i*NF + f], m);
    }
}

// ---------------- force += fdelta; fdelta=0; emit hi/lo ----------------
__global__ void force_update_k2(float* __restrict__ force, float* __restrict__ fdelta,
                                bf16* __restrict__ fhi, bf16* __restrict__ flo)
{
    int idx = blockIdx.x * blockDim.x + threadIdx.x;
    float v = force[idx] + fdelta[idx];
    force[idx] = v;
    fdelta[idx] = 0.f;
    bf16 hb, lb; split_bf16(v, hb, lb);
    fhi[idx] = hb; flo[idx] = lb;
}

// ---------------- host ----------------
extern "C" void kernel_launch(void* const* d_in, const int* in_sizes, int n_in,
                              void* d_out, int out_size)
{
    const int*   z        = (const int*)  d_in[0];
    const float* pos      = (const float*)d_in[1];
    const int*   ei       = (const int*)  d_in[4];
    const float* node_emb = (const float*)d_in[5];
    const float* mnp_W1   = (const float*)d_in[6];
    const float* mnp_b1   = (const float*)d_in[7];
    const float* mnp_W2   = (const float*)d_in[8];
    const float* mnp_b2   = (const float*)d_in[9];
    const float* me_W     = (const float*)d_in[10];
    const float* em1_W1   = (const float*)d_in[11];
    const float* em1_W2   = (const float*)d_in[12];
    const float* em2_W1   = (const float*)d_in[13];
    const float* em2_W2   = (const float*)d_in[14];
    const float* eu_W     = (const float*)d_in[15];

    float* atom = (float*)d_out;
    float* force;

    float *dist, *dir, *h, *fdelta, *force_fb;
    bf16 *bhi1, *blo1, *bhi2, *blo2, *whi, *wlo;
    cudaGetSymbolAddress((void**)&dist,     g_dist);
    cudaGetSymbolAddress((void**)&dir,      g_dir);
    cudaGetSymbolAddress((void**)&h,        g_h);
    cudaGetSymbolAddress((void**)&fdelta,   g_fdelta);
    cudaGetSymbolAddress((void**)&force_fb, g_force_fb);
    cudaGetSymbolAddress((void**)&bhi1, g_bhi1);
    cudaGetSymbolAddress((void**)&blo1, g_blo1);
    cudaGetSymbolAddress((void**)&bhi2, g_bhi2);
    cudaGetSymbolAddress((void**)&blo2, g_blo2);
    cudaGetSymbolAddress((void**)&whi,  g_whi);
    cudaGetSymbolAddress((void**)&wlo,  g_wlo);

    if (out_size >= N_NODES * (NF + 3 * NF)) force = atom + (size_t)N_NODES * NF;
    else                                     force = force_fb;

    cudaFuncSetAttribute(fused_chain1_k,   cudaFuncAttributeMaxDynamicSharedMemorySize, FUSED_SM);
    cudaFuncSetAttribute(chain2_scatter_k, cudaFuncAttributeMaxDynamicSharedMemorySize, FUSED_SM);
    cudaFuncSetAttribute(gemm_atom_k,      cudaFuncAttributeMaxDynamicSharedMemorySize, GA_SM);
    cudaFuncSetAttribute(prep_all_k,       cudaFuncAttributeMaxDynamicSharedMemorySize, PREP_SM);

    prep_all_k<<<21, 256, PREP_SM>>>(mnp_W1, mnp_W2, em1_W1, em1_W2, em2_W1, em2_W2, eu_W,
                                     whi, wlo);

    cudaMemsetAsync(force,  0, (size_t)N_NODES * 3 * NF * sizeof(float), 0);
    cudaMemsetAsync(fdelta, 0, (size_t)N_NODES * 3 * NF * sizeof(float), 0);

    init_atom_k<<<(N_NODES * NF) / 256, 256>>>(z, node_emb, atom);
    edge_embed_k<<<(N_EDGES + 255) / 256, 256>>>(pos, ei, dist, dir);

    const int GN  = (N_NODES + 127) / 128;       // 79
    const int GE  = N_EDGES / 128;               // 1250
    const int GF3 = (N_NODES * 3 + 127) / 128;   // 235

    for (int l = 0; l < NLAYERS; l++) {
        const bf16* Whi = whi + (size_t)l * 7 * 16384;
        const bf16* Wlo = wlo + (size_t)l * 7 * 16384;
        const float* b1 = mnp_b1 + (size_t)l * NF;
        const float* b2 = mnp_b2 + (size_t)l * NF;
        const float* mW = me_W   + (size_t)l * NB * NF;

        // atom -> hi/lo
        conv_k<<<(N_NODES * NF / 4 + 255) / 256, 256>>>(atom, bhi1, blo1, N_NODES * NF / 4);

        // h = silu(atom@W1+b1)@W2+b2
        fused_chain1_k<<<GN, 256, FUSED_SM>>>(
            bhi1, blo1,
            Whi + 0*16384, Wlo + 0*16384, Whi + 1*16384, Wlo + 1*16384,
            b1, b2, h, N_NODES);

        // msg (hi/lo) + atom segsum
        msg_k2<<<N_EDGES / 32, NF>>>(h, dist, ei, mW, bhi1, blo1, atom);

        // fused: p1/p2 chains + scatter into fdelta (no p1/p2 round-trip)
        chain2_scatter_k<<<GE, 256, FUSED_SM>>>(
            bhi1, blo1,
            Whi + 2*16384, Wlo + 2*16384, Whi + 3*16384, Wlo + 3*16384,
            Whi + 4*16384, Wlo + 4*16384, Whi + 5*16384, Wlo + 5*16384,
            ei, dir, force, fdelta);

        // force += fdelta; emits hi/lo
        force_update_k2<<<(N_NODES * 3 * NF) / 256, 256>>>(force, fdelta, bhi2, blo2);

        // atom += sum_d force * (force@euW)
        gemm_atom_k<<<GF3, 256, GA_SM>>>(bhi2, blo2, Whi + 6*16384, Wlo + 6*16384,
                                         force, atom, N_NODES * 3);
    }
}

// round 16
// speedup vs baseline: 1.2537x; 1.1926x over previous
#include <cuda_runtime.h>
#include <cuda_bf16.h>
#include <math.h>
#include <stdint.h>

#define N_NODES 10000
#define N_EDGES 160000
#define NF 128
#define NB 20
#define NLAYERS 3
#define CUTOFF_R 5.0f

typedef __nv_bfloat16 bf16;

// ---------------- device scratch ----------------
__device__ float g_dist[(size_t)N_EDGES * NB];
__device__ float g_dir[(size_t)N_EDGES * 3];
__device__ float g_h[(size_t)N_NODES * NF];
__device__ float g_fdelta[(size_t)N_NODES * 3 * NF];
__device__ float g_force_fb[(size_t)N_NODES * 3 * NF];
__device__ bf16 g_bhi1[(size_t)N_EDGES * NF];       // atom / msg hi
__device__ bf16 g_blo1[(size_t)N_EDGES * NF];
__device__ bf16 g_bhi2[(size_t)N_NODES * 3 * NF];   // force hi
__device__ bf16 g_blo2[(size_t)N_NODES * 3 * NF];
__device__ bf16 g_whi[21 * 16384];
__device__ bf16 g_wlo[21 * 16384];

// ============================ helpers ============================
__device__ __forceinline__ uint32_t smem_u32(const void* p) {
    uint32_t a;
    asm("{ .reg .u64 t; cvta.to.shared.u64 t, %1; cvt.u32.u64 %0, t; }" : "=r"(a) : "l"(p));
    return a;
}
__device__ __forceinline__ void ldsm_x4(uint32_t* r, uint32_t addr) {
    asm volatile("ldmatrix.sync.aligned.m8n8.x4.shared.b16 {%0,%1,%2,%3}, [%4];"
                 : "=r"(r[0]), "=r"(r[1]), "=r"(r[2]), "=r"(r[3]) : "r"(addr));
}
__device__ __forceinline__ void mma_bf16(float* d, const uint32_t* a, uint32_t b0, uint32_t b1) {
    asm volatile(
        "mma.sync.aligned.m16n8k16.row.col.f32.bf16.bf16.f32 "
        "{%0,%1,%2,%3},{%4,%5,%6,%7},{%8,%9},{%0,%1,%2,%3};"
        : "+f"(d[0]), "+f"(d[1]), "+f"(d[2]), "+f"(d[3])
        : "r"(a[0]), "r"(a[1]), "r"(a[2]), "r"(a[3]), "r"(b0), "r"(b1));
}
__device__ __forceinline__ void split_bf16(float v, bf16& h, bf16& l) {
    h = __float2bfloat16(v);
    l = __float2bfloat16(v - __bfloat162float(h));
}

// ---------------- weight prep (all 21 matrices, one launch) ----------------
#define PREP_SM (2 * 128 * 136 * 2)
__global__ void prep_all_k(const float* __restrict__ W1, const float* __restrict__ W2,
                           const float* __restrict__ W3, const float* __restrict__ W4,
                           const float* __restrict__ W5, const float* __restrict__ W6,
                           const float* __restrict__ W7,
                           bf16* __restrict__ dhi, bf16* __restrict__ dlo)
{
    extern __shared__ char sm[];
    bf16* shi = (bf16*)sm;
    bf16* slo = (bf16*)(sm + 128 * 136 * 2);
    const int tid = threadIdx.x;
    const int fam = blockIdx.x / 3;
    const int lyr = blockIdx.x % 3;
    const float* srcs[7] = {W1, W2, W3, W4, W5, W6, W7};
    const float4* s4 = reinterpret_cast<const float4*>(srcs[fam] + (size_t)lyr * 16384);
    #pragma unroll 4
    for (int q = 0; q < 16; q++) {
        int lin = q * 256 + tid;
        int k = lin >> 5, n4 = (lin & 31) << 2;
        float4 v = s4[lin];
        float vv[4] = {v.x, v.y, v.z, v.w};
        #pragma unroll
        for (int t = 0; t < 4; t++) {
            bf16 hb, lb; split_bf16(vv[t], hb, lb);
            shi[(n4 + t) * 136 + k] = hb;
            slo[(n4 + t) * 136 + k] = lb;
        }
    }
    __syncthreads();
    size_t dslot = (size_t)(lyr * 7 + fam) * 16384;
    uint4* dh4 = reinterpret_cast<uint4*>(dhi + dslot);
    uint4* dl4 = reinterpret_cast<uint4*>(dlo + dslot);
    const char* smc = sm;
    #pragma unroll 4
    for (int q = 0; q < 8; q++) {
        int lin = q * 256 + tid;
        int row = lin >> 4, seg = lin & 15;
        dh4[lin] = *(const uint4*)(smc + row * 272 + seg * 16);
        dl4[lin] = *(const uint4*)(smc + 128 * 136 * 2 + row * 272 + seg * 16);
    }
}

// ---------------- fp32 -> bf16 hi/lo ----------------
__global__ void conv_k(const float* __restrict__ x, bf16* __restrict__ hi,
                       bf16* __restrict__ lo, int n4)
{
    int i = blockIdx.x * blockDim.x + threadIdx.x;
    if (i >= n4) return;
    float4 v = reinterpret_cast<const float4*>(x)[i];
    float vv[4] = {v.x, v.y, v.z, v.w};
    uint16_t h[4], l[4];
    #pragma unroll
    for (int t = 0; t < 4; t++) {
        bf16 hb, lb; split_bf16(vv[t], hb, lb);
        h[t] = __bfloat16_as_ushort(hb); l[t] = __bfloat16_as_ushort(lb);
    }
    reinterpret_cast<uint2*>(hi)[i] = make_uint2((uint32_t)h[0] | ((uint32_t)h[1] << 16),
                                                 (uint32_t)h[2] | ((uint32_t)h[3] << 16));
    reinterpret_cast<uint2*>(lo)[i] = make_uint2((uint32_t)l[0] | ((uint32_t)l[1] << 16),
                                                 (uint32_t)l[2] | ((uint32_t)l[3] << 16));
}

// ============================ fused HMMA machinery (512 threads) ============================
#define LDA 136
#define REG_B 34816
#define SM_A  0
#define SM_B  (2 * REG_B)
#define SM_T  (4 * REG_B)
#define SM_BI (6 * REG_B)
#define FUSED_SM (6 * REG_B + 1024)
#define GA_SM   (4 * REG_B + 1024)
#define NTHR 512

__device__ __forceinline__ void load_tile_full(char* sm, int dst, const bf16* hi,
                                               const bf16* lo, int tid)
{
    const uint4* h4 = reinterpret_cast<const uint4*>(hi);
    const uint4* l4 = reinterpret_cast<const uint4*>(lo);
    #pragma unroll
    for (int q = 0; q < 4; q++) {
        int lin = q * NTHR + tid;            // 2048
        int row = lin >> 4, seg = lin & 15;
        *(uint4*)(sm + dst + row * 272 + seg * 16) = h4[lin];
        *(uint4*)(sm + dst + REG_B + row * 272 + seg * 16) = l4[lin];
    }
}
__device__ __forceinline__ void load_tile_bounded(char* sm, int dst, const bf16* hi,
                                                  const bf16* lo, int m0, int M, int tid)
{
    const uint4* h4 = reinterpret_cast<const uint4*>(hi);
    const uint4* l4 = reinterpret_cast<const uint4*>(lo);
    #pragma unroll
    for (int q = 0; q < 4; q++) {
        int lin = q * NTHR + tid;
        int row = lin >> 4, seg = lin & 15;
        uint4 vh = make_uint4(0u,0u,0u,0u), vl = make_uint4(0u,0u,0u,0u);
        if (m0 + row < M) {
            size_t gi = (size_t)(m0 + row) * 16 + seg;
            vh = h4[gi]; vl = l4[gi];
        }
        *(uint4*)(sm + dst + row * 272 + seg * 16) = vh;
        *(uint4*)(sm + dst + REG_B + row * 272 + seg * 16) = vl;
    }
}

// 16-warp stage: warp tile 32 rows x 32 cols; acc[2][4][4]
__device__ __forceinline__ void do_mma_stage(uint32_t smb, uint32_t aoff, uint32_t boff,
                                             int lane, int warp_m, int warp_n,
                                             float acc[2][4][4])
{
    #pragma unroll
    for (int mt = 0; mt < 2; mt++)
        #pragma unroll
        for (int nt = 0; nt < 4; nt++)
            #pragma unroll
            for (int r = 0; r < 4; r++) acc[mt][nt][r] = 0.f;

    const int a_row  = warp_m * 32 + (lane & 15);
    const int a_koff = (lane >> 4) << 3;
    const uint32_t sa_hi = smb + aoff + ((uint32_t)a_row * LDA + a_koff) * 2;
    const uint32_t sa_lo = sa_hi + REG_B;
    const int b_n    = warp_n * 32 + (lane & 7) + ((lane >> 4) << 3);
    const int b_koff = ((lane >> 3) & 1) << 3;
    const uint32_t sb_hi = smb + boff + ((uint32_t)b_n * LDA + b_koff) * 2;
    const uint32_t sb_lo = sb_hi + REG_B;

    #pragma unroll 2
    for (int kt = 0; kt < 8; kt++) {
        const uint32_t kb = kt * 32;
        uint32_t ah[2][4], al[2][4];
        ldsm_x4(ah[0], sa_hi + kb);
        ldsm_x4(ah[1], sa_hi + 16 * LDA * 2 + kb);
        ldsm_x4(al[0], sa_lo + kb);
        ldsm_x4(al[1], sa_lo + 16 * LDA * 2 + kb);
        uint32_t bh[2][4], bl[2][4];
        #pragma unroll
        for (int p = 0; p < 2; p++) {
            ldsm_x4(bh[p], sb_hi + (uint32_t)p * 16 * LDA * 2 + kb);
            ldsm_x4(bl[p], sb_lo + (uint32_t)p * 16 * LDA * 2 + kb);
        }
        #pragma unroll
        for (int mt = 0; mt < 2; mt++)
            #pragma unroll
            for (int p = 0; p < 2; p++)
                #pragma unroll
                for (int hf = 0; hf < 2; hf++) {
                    int nt = p * 2 + hf;
                    mma_bf16(acc[mt][nt], ah[mt], bh[p][hf*2], bh[p][hf*2+1]);
                    mma_bf16(acc[mt][nt], ah[mt], bl[p][hf*2], bl[p][hf*2+1]);
                    mma_bf16(acc[mt][nt], al[mt], bh[p][hf*2], bh[p][hf*2+1]);
                }
    }
}

template<bool BIAS>
__device__ __forceinline__ void store_T(char* sm, float acc[2][4][4], const float* sbias,
                                        int lane, int warp_m, int warp_n)
{
    #pragma unroll
    for (int mt = 0; mt < 2; mt++) {
        #pragma unroll
        for (int nt = 0; nt < 4; nt++) {
            int col = warp_n * 32 + nt * 8 + ((lane & 3) << 1);
            #pragma unroll
            for (int half = 0; half < 2; half++) {
                int r = warp_m * 32 + mt * 16 + (lane >> 2) + half * 8;
                float x0 = acc[mt][nt][half*2+0], x1 = acc[mt][nt][half*2+1];
                if (BIAS) { x0 += sbias[col]; x1 += sbias[col+1]; }
                x0 = x0 / (1.0f + expf(-x0));
                x1 = x1 / (1.0f + expf(-x1));
                bf16 h0, l0, h1, l1;
                split_bf16(x0, h0, l0); split_bf16(x1, h1, l1);
                uint32_t off = ((uint32_t)r * LDA + col) * 2;
                *(uint32_t*)(sm + SM_T + off) = (uint32_t)__bfloat16_as_ushort(h0)
                                              | ((uint32_t)__bfloat16_as_ushort(h1) << 16);
                *(uint32_t*)(sm + SM_T + REG_B + off) = (uint32_t)__bfloat16_as_ushort(l0)
                                              | ((uint32_t)__bfloat16_as_ushort(l1) << 16);
            }
        }
    }
}

template<bool BIAS>
__device__ __forceinline__ void store_out(float* out, float acc[2][4][4], const float* sbias,
                                          int m0, int M, int lane, int warp_m, int warp_n)
{
    #pragma unroll
    for (int mt = 0; mt < 2; mt++) {
        int r0 = m0 + warp_m * 32 + mt * 16 + (lane >> 2);
        #pragma unroll
        for (int nt = 0; nt < 4; nt++) {
            int col = warp_n * 32 + nt * 8 + ((lane & 3) << 1);
            float v[4];
            #pragma unroll
            for (int r = 0; r < 4; r++) {
                float x = acc[mt][nt][r];
                if (BIAS) x += sbias[col + (r & 1)];
                v[r] = x;
            }
            if (r0 < M)     *(float2*)&out[(size_t)r0 * NF + col]       = make_float2(v[0], v[1]);
            if (r0 + 8 < M) *(float2*)&out[(size_t)(r0 + 8) * NF + col] = make_float2(v[2], v[3]);
        }
    }
}

// ---------------- node chain: h = silu(A@W1+b1)@W2+b2 ----------------
__global__ void __launch_bounds__(NTHR) fused_chain1_k(
    const bf16* __restrict__ Ahi, const bf16* __restrict__ Alo,
    const bf16* __restrict__ W1hi, const bf16* __restrict__ W1lo,
    const bf16* __restrict__ W2hi, const bf16* __restrict__ W2lo,
    const float* __restrict__ bias1, const float* __restrict__ bias2,
    float* __restrict__ out1, int M)
{
    extern __shared__ char sm[];
    const uint32_t smb = smem_u32(sm);
    const int tid  = threadIdx.x;
    const int lane = tid & 31;
    const int warp = tid >> 5;
    const int warp_m = warp & 3;
    const int warp_n = warp >> 2;
    const int m0   = blockIdx.x * 128;

    float* sb1 = (float*)(sm + SM_BI);
    float* sb2 = (float*)(sm + SM_BI + 512);
    if (tid < 128) { sb1[tid] = bias1[tid]; sb2[tid] = bias2[tid]; }

    load_tile_bounded(sm, SM_A, Ahi, Alo, m0, M, tid);
    load_tile_full(sm, SM_B, W1hi, W1lo, tid);
    __syncthreads();

    float acc[2][4][4];
    do_mma_stage(smb, SM_A, SM_B, lane, warp_m, warp_n, acc);
    store_T<true>(sm, acc, sb1, lane, warp_m, warp_n);
    __syncthreads();
    load_tile_full(sm, SM_B, W2hi, W2lo, tid);
    __syncthreads();
    do_mma_stage(smb, SM_T, SM_B, lane, warp_m, warp_n, acc);
    store_out<true>(out1, acc, sb2, m0, M, lane, warp_m, warp_n);
}

// ---------------- edge chain + fused scatter ----------------
__global__ void __launch_bounds__(NTHR) chain2_scatter_k(
    const bf16* __restrict__ Ahi, const bf16* __restrict__ Alo,
    const bf16* __restrict__ W1hi, const bf16* __restrict__ W1lo,
    const bf16* __restrict__ W2hi, const bf16* __restrict__ W2lo,
    const bf16* __restrict__ W3hi, const bf16* __restrict__ W3lo,
    const bf16* __restrict__ W4hi, const bf16* __restrict__ W4lo,
    const int* __restrict__ ei, const float* __restrict__ dir,
    const float* __restrict__ force, float* __restrict__ fdelta)
{
    extern __shared__ char sm[];
    const uint32_t smb = smem_u32(sm);
    const int tid  = threadIdx.x;
    const int lane = tid & 31;
    const int warp = tid >> 5;
    const int warp_m = warp & 3;
    const int warp_n = warp >> 2;
    const int m0   = blockIdx.x * 128;      // E % 128 == 0

    load_tile_full(sm, SM_A, Ahi + (size_t)m0 * NF, Alo + (size_t)m0 * NF, tid);
    load_tile_full(sm, SM_B, W1hi, W1lo, tid);
    __syncthreads();

    float acc[2][4][4];
    // stage 1-2 -> p1 (stashed)
    do_mma_stage(smb, SM_A, SM_B, lane, warp_m, warp_n, acc);
    store_T<false>(sm, acc, nullptr, lane, warp_m, warp_n);
    __syncthreads();
    load_tile_full(sm, SM_B, W2hi, W2lo, tid);
    __syncthreads();
    do_mma_stage(smb, SM_T, SM_B, lane, warp_m, warp_n, acc);

    float p1r[2][4][4];
    #pragma unroll
    for (int mt = 0; mt < 2; mt++)
        #pragma unroll
        for (int nt = 0; nt < 4; nt++)
            #pragma unroll
            for (int r = 0; r < 4; r++) p1r[mt][nt][r] = acc[mt][nt][r];

    // stage 3-4 -> p2
    __syncthreads();
    load_tile_full(sm, SM_B, W3hi, W3lo, tid);
    __syncthreads();
    do_mma_stage(smb, SM_A, SM_B, lane, warp_m, warp_n, acc);
    store_T<false>(sm, acc, nullptr, lane, warp_m, warp_n);
    __syncthreads();
    load_tile_full(sm, SM_B, W4hi, W4lo, tid);
    __syncthreads();
    do_mma_stage(smb, SM_T, SM_B, lane, warp_m, warp_n, acc);

    // fused scatter epilogue
    #pragma unroll
    for (int mt = 0; mt < 2; mt++) {
        #pragma unroll
        for (int half = 0; half < 2; half++) {
            int e = m0 + warp_m * 32 + mt * 16 + (lane >> 2) + half * 8;
            int i = ei[e], j = ei[N_EDGES + e];
            float ddir[3];
            ddir[0] = dir[e*3+0]; ddir[1] = dir[e*3+1]; ddir[2] = dir[e*3+2];
            const float* fj = &force[(size_t)j * 3 * NF];
            float* fd = &fdelta[(size_t)i * 3 * NF];
            #pragma unroll
            for (int nt = 0; nt < 4; nt++) {
                int col = warp_n * 32 + nt * 8 + ((lane & 3) << 1);
                float v1a = p1r[mt][nt][half*2+0], v1b = p1r[mt][nt][half*2+1];
                float v2a = acc[mt][nt][half*2+0], v2b = acc[mt][nt][half*2+1];
                #pragma unroll
                for (int d = 0; d < 3; d++) {
                    float2 f = *(const float2*)&fj[d*NF + col];
                    atomicAdd(&fd[d*NF + col],     fmaf(v1a, ddir[d], v2a * f.x));
                    atomicAdd(&fd[d*NF + col + 1], fmaf(v1b, ddir[d], v2b * f.y));
                }
            }
        }
    }
}

// ---------------- g = force@euW fused with atom += sum_d force*g ----------------
__global__ void __launch_bounds__(NTHR) gemm_atom_k(
    const bf16* __restrict__ Fhi, const bf16* __restrict__ Flo,
    const bf16* __restrict__ Whi, const bf16* __restrict__ Wlo,
    const float* __restrict__ force, float* __restrict__ atom, int M)
{
    extern __shared__ char sm[];
    const uint32_t smb = smem_u32(sm);
    const int tid  = threadIdx.x;
    const int lane = tid & 31;
    const int warp = tid >> 5;
    const int warp_m = warp & 3;
    const int warp_n = warp >> 2;
    const int m0   = blockIdx.x * 128;

    load_tile_bounded(sm, SM_A, Fhi, Flo, m0, M, tid);
    load_tile_full(sm, SM_B, Whi, Wlo, tid);
    __syncthreads();

    float acc[2][4][4];
    do_mma_stage(smb, SM_A, SM_B, lane, warp_m, warp_n, acc);

    #pragma unroll
    for (int mt = 0; mt < 2; mt++) {
        #pragma unroll
        for (int half = 0; half < 2; half++) {
            int r = m0 + warp_m * 32 + mt * 16 + (lane >> 2) + half * 8;
            if (r >= M) continue;
            int n = r / 3;
            #pragma unroll
            for (int nt = 0; nt < 4; nt++) {
                int col = warp_n * 32 + nt * 8 + ((lane & 3) << 1);
                float2 f = *(const float2*)&force[(size_t)r * NF + col];
                atomicAdd(&atom[(size_t)n * NF + col],     acc[mt][nt][half*2+0] * f.x);
                atomicAdd(&atom[(size_t)n * NF + col + 1], acc[mt][nt][half*2+1] * f.y);
            }
        }
    }
}

// ---------------- init: atom = node_emb[z] ----------------
__global__ void init_atom_k(const int* __restrict__ z, const float* __restrict__ emb,
                            float* __restrict__ atom)
{
    int idx = blockIdx.x * blockDim.x + threadIdx.x;
    int n = idx >> 7, f = idx & 127;
    atom[idx] = emb[(size_t)z[n] * NF + f];
}

// ---------------- edge embedding ----------------
__global__ void edge_embed_k(const float* __restrict__ pos, const int* __restrict__ ei,
                             float* __restrict__ dist, float* __restrict__ dir)
{
    int e = blockIdx.x * blockDim.x + threadIdx.x;
    if (e >= N_EDGES) return;
    int i = ei[e], j = ei[N_EDGES + e];
    float dx = pos[j*3+0] - pos[i*3+0];
    float dy = pos[j*3+1] - pos[i*3+1];
    float dz = pos[j*3+2] - pos[i*3+2];
    float d = sqrtf(dx*dx + dy*dy + dz*dz + 1e-12f);
    float inv = 1.0f / d;
    dir[e*3+0] = dx*inv; dir[e*3+1] = dy*inv; dir[e*3+2] = dz*inv;
    float fc = (d < CUTOFF_R) ? 0.5f * (cosf(3.14159265358979323846f * d / CUTOFF_R) + 1.0f) : 0.0f;
    const float inv_w = 1.0f / (CUTOFF_R / NB);
    #pragma unroll
    for (int b = 0; b < NB; b++) {
        float c = CUTOFF_R * (float)b / (float)(NB - 1);
        float t = (d - c) * inv_w;
        dist[(size_t)e*NB + b] = expf(-t*t) * fc;
    }
}

// ---------------- msg = (dist@meW)*h[i]*h[j] -> hi/lo; atom += segsum ----------------
__global__ void msg_k2(const float* __restrict__ h, const float* __restrict__ dist,
                       const int* __restrict__ ei, const float* __restrict__ meW,
                       bf16* __restrict__ mhi, bf16* __restrict__ mlo,
                       float* __restrict__ atom)
{
    __shared__ float sW[NB * NF];
    __shared__ float sd[32 * NB];
    int f = threadIdx.x;
    #pragma unroll
    for (int b = 0; b < NB; b++) sW[b*NF + f] = meW[b*NF + f];
    int e0 = blockIdx.x * 32;
    for (int q = f; q < 32 * NB; q += NF) sd[q] = dist[(size_t)e0 * NB + q];
    __syncthreads();
    #pragma unroll 2
    for (int t = 0; t < 32; t++) {
        int e = e0 + t;
        int i = ei[e], j = ei[N_EDGES + e];
        float me = 0.f;
        #pragma unroll
        for (int b = 0; b < NB; b++) me = fmaf(sd[t*NB + b], sW[b*NF + f], me);
        float m = me * h[(size_t)i*NF + f] * h[(size_t)j*NF + f];
        bf16 hb, lb; split_bf16(m, hb, lb);
        mhi[(size_t)e*NF + f] = hb;
        mlo[(size_t)e*NF + f] = lb;
        atomicAdd(&atom[(size_t)i*NF + f], m);
    }
}

// ---------------- force += fdelta; fdelta=0; emit hi/lo ----------------
__global__ void force_update_k2(float* __restrict__ force, float* __restrict__ fdelta,
                                bf16* __restrict__ fhi, bf16* __restrict__ flo)
{
    int idx = blockIdx.x * blockDim.x + threadIdx.x;
    float v = force[idx] + fdelta[idx];
    force[idx] = v;
    fdelta[idx] = 0.f;
    bf16 hb, lb; split_bf16(v, hb, lb);
    fhi[idx] = hb; flo[idx] = lb;
}

// ---------------- host ----------------
extern "C" void kernel_launch(void* const* d_in, const int* in_sizes, int n_in,
                              void* d_out, int out_size)
{
    const int*   z        = (const int*)  d_in[0];
    const float* pos      = (const float*)d_in[1];
    const int*   ei       = (const int*)  d_in[4];
    const float* node_emb = (const float*)d_in[5];
    const float* mnp_W1   = (const float*)d_in[6];
    const float* mnp_b1   = (const float*)d_in[7];
    const float* mnp_W2   = (const float*)d_in[8];
    const float* mnp_b2   = (const float*)d_in[9];
    const float* me_W     = (const float*)d_in[10];
    const float* em1_W1   = (const float*)d_in[11];
    const float* em1_W2   = (const float*)d_in[12];
    const float* em2_W1   = (const float*)d_in[13];
    const float* em2_W2   = (const float*)d_in[14];
    const float* eu_W     = (const float*)d_in[15];

    float* atom = (float*)d_out;
    float* force;

    float *dist, *dir, *h, *fdelta, *force_fb;
    bf16 *bhi1, *blo1, *bhi2, *blo2, *whi, *wlo;
    cudaGetSymbolAddress((void**)&dist,     g_dist);
    cudaGetSymbolAddress((void**)&dir,      g_dir);
    cudaGetSymbolAddress((void**)&h,        g_h);
    cudaGetSymbolAddress((void**)&fdelta,   g_fdelta);
    cudaGetSymbolAddress((void**)&force_fb, g_force_fb);
    cudaGetSymbolAddress((void**)&bhi1, g_bhi1);
    cudaGetSymbolAddress((void**)&blo1, g_blo1);
    cudaGetSymbolAddress((void**)&bhi2, g_bhi2);
    cudaGetSymbolAddress((void**)&blo2, g_blo2);
    cudaGetSymbolAddress((void**)&whi,  g_whi);
    cudaGetSymbolAddress((void**)&wlo,  g_wlo);

    if (out_size >= N_NODES * (NF + 3 * NF)) force = atom + (size_t)N_NODES * NF;
    else                                     force = force_fb;

    cudaFuncSetAttribute(fused_chain1_k,   cudaFuncAttributeMaxDynamicSharedMemorySize, FUSED_SM);
    cudaFuncSetAttribute(chain2_scatter_k, cudaFuncAttributeMaxDynamicSharedMemorySize, FUSED_SM);
    cudaFuncSetAttribute(gemm_atom_k,      cudaFuncAttributeMaxDynamicSharedMemorySize, GA_SM);
    cudaFuncSetAttribute(prep_all_k,       cudaFuncAttributeMaxDynamicSharedMemorySize, PREP_SM);

    prep_all_k<<<21, 256, PREP_SM>>>(mnp_W1, mnp_W2, em1_W1, em1_W2, em2_W1, em2_W2, eu_W,
                                     whi, wlo);

    cudaMemsetAsync(force,  0, (size_t)N_NODES * 3 * NF * sizeof(float), 0);
    cudaMemsetAsync(fdelta, 0, (size_t)N_NODES * 3 * NF * sizeof(float), 0);

    init_atom_k<<<(N_NODES * NF) / 256, 256>>>(z, node_emb, atom);
    edge_embed_k<<<(N_EDGES + 255) / 256, 256>>>(pos, ei, dist, dir);

    const int GN  = (N_NODES + 127) / 128;       // 79
    const int GE  = N_EDGES / 128;               // 1250
    const int GF3 = (N_NODES * 3 + 127) / 128;   // 235

    for (int l = 0; l < NLAYERS; l++) {
        const bf16* Whi = whi + (size_t)l * 7 * 16384;
        const bf16* Wlo = wlo + (size_t)l * 7 * 16384;
        const float* b1 = mnp_b1 + (size_t)l * NF;
        const float* b2 = mnp_b2 + (size_t)l * NF;
        const float* mW = me_W   + (size_t)l * NB * NF;

        // atom -> hi/lo
        conv_k<<<(N_NODES * NF / 4 + 255) / 256, 256>>>(atom, bhi1, blo1, N_NODES * NF / 4);

        // h = silu(atom@W1+b1)@W2+b2
        fused_chain1_k<<<GN, NTHR, FUSED_SM>>>(
            bhi1, blo1,
            Whi + 0*16384, Wlo + 0*16384, Whi + 1*16384, Wlo + 1*16384,
            b1, b2, h, N_NODES);

        // msg (hi/lo) + atom segsum
        msg_k2<<<N_EDGES / 32, NF>>>(h, dist, ei, mW, bhi1, blo1, atom);

        // fused: p1/p2 chains + scatter into fdelta
        chain2_scatter_k<<<GE, NTHR, FUSED_SM>>>(
            bhi1, blo1,
            Whi + 2*16384, Wlo + 2*16384, Whi + 3*16384, Wlo + 3*16384,
            Whi + 4*16384, Wlo + 4*16384, Whi + 5*16384, Wlo + 5*16384,
            ei, dir, force, fdelta);

        // force += fdelta; emits hi/lo
        force_update_k2<<<(N_NODES * 3 * NF) / 256, 256>>>(force, fdelta, bhi2, blo2);

        // atom += sum_d force * (force@euW)
        gemm_atom_k<<<GF3, NTHR, GA_SM>>>(bhi2, blo2, Whi + 6*16384, Wlo + 6*16384,
                                          force, atom, N_NODES * 3);
    }
}

// round 17
// speedup vs baseline: 1.2626x; 1.0070x over previous
#include <cuda_runtime.h>
#include <cuda_bf16.h>
#include <math.h>
#include <stdint.h>

#define N_NODES 10000
#define N_EDGES 160000
#define NF 128
#define NB 20
#define NLAYERS 3
#define CUTOFF_R 5.0f

typedef __nv_bfloat16 bf16;

// ---------------- device scratch ----------------
__device__ float g_dist[(size_t)N_EDGES * NB];
__device__ float g_dir[(size_t)N_EDGES * 3];
__device__ float g_h[(size_t)N_NODES * NF];
__device__ float g_fdelta[(size_t)N_NODES * 3 * NF];
__device__ float g_force_fb[(size_t)N_NODES * 3 * NF];
__device__ bf16 g_bhi1[(size_t)N_EDGES * NF];       // atom / msg hi
__device__ bf16 g_blo1[(size_t)N_EDGES * NF];
__device__ bf16 g_bhi2[(size_t)N_NODES * 3 * NF];   // force hi
__device__ bf16 g_blo2[(size_t)N_NODES * 3 * NF];
__device__ bf16 g_whi[21 * 16384];
__device__ bf16 g_wlo[21 * 16384];

// ============================ helpers ============================
__device__ __forceinline__ uint32_t smem_u32(const void* p) {
    uint32_t a;
    asm("{ .reg .u64 t; cvta.to.shared.u64 t, %1; cvt.u32.u64 %0, t; }" : "=r"(a) : "l"(p));
    return a;
}
__device__ __forceinline__ void ldsm_x4(uint32_t* r, uint32_t addr) {
    asm volatile("ldmatrix.sync.aligned.m8n8.x4.shared.b16 {%0,%1,%2,%3}, [%4];"
                 : "=r"(r[0]), "=r"(r[1]), "=r"(r[2]), "=r"(r[3]) : "r"(addr));
}
__device__ __forceinline__ void mma_bf16(float* d, const uint32_t* a, uint32_t b0, uint32_t b1) {
    asm volatile(
        "mma.sync.aligned.m16n8k16.row.col.f32.bf16.bf16.f32 "
        "{%0,%1,%2,%3},{%4,%5,%6,%7},{%8,%9},{%0,%1,%2,%3};"
        : "+f"(d[0]), "+f"(d[1]), "+f"(d[2]), "+f"(d[3])
        : "r"(a[0]), "r"(a[1]), "r"(a[2]), "r"(a[3]), "r"(b0), "r"(b1));
}
__device__ __forceinline__ void split_bf16(float v, bf16& h, bf16& l) {
    h = __float2bfloat16(v);
    l = __float2bfloat16(v - __bfloat162float(h));
}

// ---------------- weight prep (all 21 matrices, one launch) ----------------
#define PREP_SM (2 * 128 * 136 * 2)
__global__ void prep_all_k(const float* __restrict__ W1, const float* __restrict__ W2,
                           const float* __restrict__ W3, const float* __restrict__ W4,
                           const float* __restrict__ W5, const float* __restrict__ W6,
                           const float* __restrict__ W7,
                           bf16* __restrict__ dhi, bf16* __restrict__ dlo)
{
    extern __shared__ char sm[];
    bf16* shi = (bf16*)sm;
    bf16* slo = (bf16*)(sm + 128 * 136 * 2);
    const int tid = threadIdx.x;
    const int fam = blockIdx.x / 3;
    const int lyr = blockIdx.x % 3;
    const float* srcs[7] = {W1, W2, W3, W4, W5, W6, W7};
    const float4* s4 = reinterpret_cast<const float4*>(srcs[fam] + (size_t)lyr * 16384);
    #pragma unroll 4
    for (int q = 0; q < 16; q++) {
        int lin = q * 256 + tid;
        int k = lin >> 5, n4 = (lin & 31) << 2;
        float4 v = s4[lin];
        float vv[4] = {v.x, v.y, v.z, v.w};
        #pragma unroll
        for (int t = 0; t < 4; t++) {
            bf16 hb, lb; split_bf16(vv[t], hb, lb);
            shi[(n4 + t) * 136 + k] = hb;
            slo[(n4 + t) * 136 + k] = lb;
        }
    }
    __syncthreads();
    size_t dslot = (size_t)(lyr * 7 + fam) * 16384;
    uint4* dh4 = reinterpret_cast<uint4*>(dhi + dslot);
    uint4* dl4 = reinterpret_cast<uint4*>(dlo + dslot);
    const char* smc = sm;
    #pragma unroll 4
    for (int q = 0; q < 8; q++) {
        int lin = q * 256 + tid;
        int row = lin >> 4, seg = lin & 15;
        dh4[lin] = *(const uint4*)(smc + row * 272 + seg * 16);
        dl4[lin] = *(const uint4*)(smc + 128 * 136 * 2 + row * 272 + seg * 16);
    }
}

// ---------------- fp32 -> bf16 hi/lo ----------------
__global__ void conv_k(const float* __restrict__ x, bf16* __restrict__ hi,
                       bf16* __restrict__ lo, int n4)
{
    int i = blockIdx.x * blockDim.x + threadIdx.x;
    if (i >= n4) return;
    float4 v = reinterpret_cast<const float4*>(x)[i];
    float vv[4] = {v.x, v.y, v.z, v.w};
    uint16_t h[4], l[4];
    #pragma unroll
    for (int t = 0; t < 4; t++) {
        bf16 hb, lb; split_bf16(vv[t], hb, lb);
        h[t] = __bfloat16_as_ushort(hb); l[t] = __bfloat16_as_ushort(lb);
    }
    reinterpret_cast<uint2*>(hi)[i] = make_uint2((uint32_t)h[0] | ((uint32_t)h[1] << 16),
                                                 (uint32_t)h[2] | ((uint32_t)h[3] << 16));
    reinterpret_cast<uint2*>(lo)[i] = make_uint2((uint32_t)l[0] | ((uint32_t)l[1] << 16),
                                                 (uint32_t)l[2] | ((uint32_t)l[3] << 16));
}

// ============================ fused HMMA machinery (512 threads) ============================
#define LDA 136
#define REG_B 34816
#define SM_A  0
#define SM_B  (2 * REG_B)
#define SM_T  (4 * REG_B)
#define SM_BI (6 * REG_B)
#define FUSED_SM (6 * REG_B + 1024)
#define GA_SM   (4 * REG_B + 1024)
#define NTHR 512

struct WReg { uint4 h[4]; uint4 l[4]; };   // one full hi/lo weight tile, 512-thr split

__device__ __forceinline__ void prefetch_w(const bf16* hi, const bf16* lo, int tid, WReg& w)
{
    const uint4* h4 = reinterpret_cast<const uint4*>(hi);
    const uint4* l4 = reinterpret_cast<const uint4*>(lo);
    #pragma unroll
    for (int q = 0; q < 4; q++) {
        w.h[q] = h4[q * NTHR + tid];
        w.l[q] = l4[q * NTHR + tid];
    }
}
__device__ __forceinline__ void commit_w(char* sm, int dst, int tid, const WReg& w)
{
    #pragma unroll
    for (int q = 0; q < 4; q++) {
        int lin = q * NTHR + tid;
        int row = lin >> 4, seg = lin & 15;
        *(uint4*)(sm + dst + row * 272 + seg * 16) = w.h[q];
        *(uint4*)(sm + dst + REG_B + row * 272 + seg * 16) = w.l[q];
    }
}

__device__ __forceinline__ void load_tile_full(char* sm, int dst, const bf16* hi,
                                               const bf16* lo, int tid)
{
    const uint4* h4 = reinterpret_cast<const uint4*>(hi);
    const uint4* l4 = reinterpret_cast<const uint4*>(lo);
    #pragma unroll
    for (int q = 0; q < 4; q++) {
        int lin = q * NTHR + tid;
        int row = lin >> 4, seg = lin & 15;
        *(uint4*)(sm + dst + row * 272 + seg * 16) = h4[lin];
        *(uint4*)(sm + dst + REG_B + row * 272 + seg * 16) = l4[lin];
    }
}
__device__ __forceinline__ void load_tile_bounded(char* sm, int dst, const bf16* hi,
                                                  const bf16* lo, int m0, int M, int tid)
{
    const uint4* h4 = reinterpret_cast<const uint4*>(hi);
    const uint4* l4 = reinterpret_cast<const uint4*>(lo);
    #pragma unroll
    for (int q = 0; q < 4; q++) {
        int lin = q * NTHR + tid;
        int row = lin >> 4, seg = lin & 15;
        uint4 vh = make_uint4(0u,0u,0u,0u), vl = make_uint4(0u,0u,0u,0u);
        if (m0 + row < M) {
            size_t gi = (size_t)(m0 + row) * 16 + seg;
            vh = h4[gi]; vl = l4[gi];
        }
        *(uint4*)(sm + dst + row * 272 + seg * 16) = vh;
        *(uint4*)(sm + dst + REG_B + row * 272 + seg * 16) = vl;
    }
}

// 16-warp stage: warp tile 32 rows x 32 cols; acc[2][4][4]
__device__ __forceinline__ void do_mma_stage(uint32_t smb, uint32_t aoff, uint32_t boff,
                                             int lane, int warp_m, int warp_n,
                                             float acc[2][4][4])
{
    #pragma unroll
    for (int mt = 0; mt < 2; mt++)
        #pragma unroll
        for (int nt = 0; nt < 4; nt++)
            #pragma unroll
            for (int r = 0; r < 4; r++) acc[mt][nt][r] = 0.f;

    const int a_row  = warp_m * 32 + (lane & 15);
    const int a_koff = (lane >> 4) << 3;
    const uint32_t sa_hi = smb + aoff + ((uint32_t)a_row * LDA + a_koff) * 2;
    const uint32_t sa_lo = sa_hi + REG_B;
    const int b_n    = warp_n * 32 + (lane & 7) + ((lane >> 4) << 3);
    const int b_koff = ((lane >> 3) & 1) << 3;
    const uint32_t sb_hi = smb + boff + ((uint32_t)b_n * LDA + b_koff) * 2;
    const uint32_t sb_lo = sb_hi + REG_B;

    #pragma unroll 2
    for (int kt = 0; kt < 8; kt++) {
        const uint32_t kb = kt * 32;
        uint32_t ah[2][4], al[2][4];
        ldsm_x4(ah[0], sa_hi + kb);
        ldsm_x4(ah[1], sa_hi + 16 * LDA * 2 + kb);
        ldsm_x4(al[0], sa_lo + kb);
        ldsm_x4(al[1], sa_lo + 16 * LDA * 2 + kb);
        uint32_t bh[2][4], bl[2][4];
        #pragma unroll
        for (int p = 0; p < 2; p++) {
            ldsm_x4(bh[p], sb_hi + (uint32_t)p * 16 * LDA * 2 + kb);
            ldsm_x4(bl[p], sb_lo + (uint32_t)p * 16 * LDA * 2 + kb);
        }
        #pragma unroll
        for (int mt = 0; mt < 2; mt++)
            #pragma unroll
            for (int p = 0; p < 2; p++)
                #pragma unroll
                for (int hf = 0; hf < 2; hf++) {
                    int nt = p * 2 + hf;
                    mma_bf16(acc[mt][nt], ah[mt], bh[p][hf*2], bh[p][hf*2+1]);
                    mma_bf16(acc[mt][nt], ah[mt], bl[p][hf*2], bl[p][hf*2+1]);
                    mma_bf16(acc[mt][nt], al[mt], bh[p][hf*2], bh[p][hf*2+1]);
                }
    }
}

template<bool BIAS>
__device__ __forceinline__ void store_T(char* sm, float acc[2][4][4], const float* sbias,
                                        int lane, int warp_m, int warp_n)
{
    #pragma unroll
    for (int mt = 0; mt < 2; mt++) {
        #pragma unroll
        for (int nt = 0; nt < 4; nt++) {
            int col = warp_n * 32 + nt * 8 + ((lane & 3) << 1);
            #pragma unroll
            for (int half = 0; half < 2; half++) {
                int r = warp_m * 32 + mt * 16 + (lane >> 2) + half * 8;
                float x0 = acc[mt][nt][half*2+0], x1 = acc[mt][nt][half*2+1];
                if (BIAS) { x0 += sbias[col]; x1 += sbias[col+1]; }
                x0 = x0 / (1.0f + expf(-x0));
                x1 = x1 / (1.0f + expf(-x1));
                bf16 h0, l0, h1, l1;
                split_bf16(x0, h0, l0); split_bf16(x1, h1, l1);
                uint32_t off = ((uint32_t)r * LDA + col) * 2;
                *(uint32_t*)(sm + SM_T + off) = (uint32_t)__bfloat16_as_ushort(h0)
                                              | ((uint32_t)__bfloat16_as_ushort(h1) << 16);
                *(uint32_t*)(sm + SM_T + REG_B + off) = (uint32_t)__bfloat16_as_ushort(l0)
                                              | ((uint32_t)__bfloat16_as_ushort(l1) << 16);
            }
        }
    }
}

template<bool BIAS>
__device__ __forceinline__ void store_out(float* out, float acc[2][4][4], const float* sbias,
                                          int m0, int M, int lane, int warp_m, int warp_n)
{
    #pragma unroll
    for (int mt = 0; mt < 2; mt++) {
        int r0 = m0 + warp_m * 32 + mt * 16 + (lane >> 2);
        #pragma unroll
        for (int nt = 0; nt < 4; nt++) {
            int col = warp_n * 32 + nt * 8 + ((lane & 3) << 1);
            float v[4];
            #pragma unroll
            for (int r = 0; r < 4; r++) {
                float x = acc[mt][nt][r];
                if (BIAS) x += sbias[col + (r & 1)];
                v[r] = x;
            }
            if (r0 < M)     *(float2*)&out[(size_t)r0 * NF + col]       = make_float2(v[0], v[1]);
            if (r0 + 8 < M) *(float2*)&out[(size_t)(r0 + 8) * NF + col] = make_float2(v[2], v[3]);
        }
    }
}

// ---------------- node chain: h = silu(A@W1+b1)@W2+b2 (W2 prefetched) ----------------
__global__ void __launch_bounds__(NTHR) fused_chain1_k(
    const bf16* __restrict__ Ahi, const bf16* __restrict__ Alo,
    const bf16* __restrict__ W1hi, const bf16* __restrict__ W1lo,
    const bf16* __restrict__ W2hi, const bf16* __restrict__ W2lo,
    const float* __restrict__ bias1, const float* __restrict__ bias2,
    float* __restrict__ out1, int M)
{
    extern __shared__ char sm[];
    const uint32_t smb = smem_u32(sm);
    const int tid  = threadIdx.x;
    const int lane = tid & 31;
    const int warp = tid >> 5;
    const int warp_m = warp & 3;
    const int warp_n = warp >> 2;
    const int m0   = blockIdx.x * 128;

    float* sb1 = (float*)(sm + SM_BI);
    float* sb2 = (float*)(sm + SM_BI + 512);
    if (tid < 128) { sb1[tid] = bias1[tid]; sb2[tid] = bias2[tid]; }

    load_tile_bounded(sm, SM_A, Ahi, Alo, m0, M, tid);
    load_tile_full(sm, SM_B, W1hi, W1lo, tid);
    __syncthreads();

    WReg w2; prefetch_w(W2hi, W2lo, tid, w2);

    float acc[2][4][4];
    do_mma_stage(smb, SM_A, SM_B, lane, warp_m, warp_n, acc);
    store_T<true>(sm, acc, sb1, lane, warp_m, warp_n);
    __syncthreads();
    commit_w(sm, SM_B, tid, w2);
    __syncthreads();
    do_mma_stage(smb, SM_T, SM_B, lane, warp_m, warp_n, acc);
    store_out<true>(out1, acc, sb2, m0, M, lane, warp_m, warp_n);
}

// ---------------- edge chain + fused scatter (W2, W3 prefetched) ----------------
__global__ void __launch_bounds__(NTHR) chain2_scatter_k(
    const bf16* __restrict__ Ahi, const bf16* __restrict__ Alo,
    const bf16* __restrict__ W1hi, const bf16* __restrict__ W1lo,
    const bf16* __restrict__ W2hi, const bf16* __restrict__ W2lo,
    const bf16* __restrict__ W3hi, const bf16* __restrict__ W3lo,
    const bf16* __restrict__ W4hi, const bf16* __restrict__ W4lo,
    const int* __restrict__ ei, const float* __restrict__ dir,
    const float* __restrict__ force, float* __restrict__ fdelta)
{
    extern __shared__ char sm[];
    const uint32_t smb = smem_u32(sm);
    const int tid  = threadIdx.x;
    const int lane = tid & 31;
    const int warp = tid >> 5;
    const int warp_m = warp & 3;
    const int warp_n = warp >> 2;
    const int m0   = blockIdx.x * 128;      // E % 128 == 0

    load_tile_full(sm, SM_A, Ahi + (size_t)m0 * NF, Alo + (size_t)m0 * NF, tid);
    load_tile_full(sm, SM_B, W1hi, W1lo, tid);
    __syncthreads();

    float acc[2][4][4];

    // stage 1 (A@W1 -> T), prefetch W2 under it
    {
        WReg w2; prefetch_w(W2hi, W2lo, tid, w2);
        do_mma_stage(smb, SM_A, SM_B, lane, warp_m, warp_n, acc);
        store_T<false>(sm, acc, nullptr, lane, warp_m, warp_n);
        __syncthreads();
        commit_w(sm, SM_B, tid, w2);
    }
    // stage 2 (T@W2 -> p1), prefetch W3 under it
    WReg w3; prefetch_w(W3hi, W3lo, tid, w3);
    __syncthreads();
    do_mma_stage(smb, SM_T, SM_B, lane, warp_m, warp_n, acc);

    float p1r[2][4][4];
    #pragma unroll
    for (int mt = 0; mt < 2; mt++)
        #pragma unroll
        for (int nt = 0; nt < 4; nt++)
            #pragma unroll
            for (int r = 0; r < 4; r++) p1r[mt][nt][r] = acc[mt][nt][r];

    __syncthreads();
    commit_w(sm, SM_B, tid, w3);
    __syncthreads();
    // stage 3 (A@W3 -> T)
    do_mma_stage(smb, SM_A, SM_B, lane, warp_m, warp_n, acc);
    store_T<false>(sm, acc, nullptr, lane, warp_m, warp_n);
    __syncthreads();
    load_tile_full(sm, SM_B, W4hi, W4lo, tid);
    __syncthreads();
    // stage 4 (T@W4 -> p2)
    do_mma_stage(smb, SM_T, SM_B, lane, warp_m, warp_n, acc);

    // fused scatter epilogue
    #pragma unroll
    for (int mt = 0; mt < 2; mt++) {
        #pragma unroll
        for (int half = 0; half < 2; half++) {
            int e = m0 + warp_m * 32 + mt * 16 + (lane >> 2) + half * 8;
            int i = ei[e], j = ei[N_EDGES + e];
            float ddir[3];
            ddir[0] = dir[e*3+0]; ddir[1] = dir[e*3+1]; ddir[2] = dir[e*3+2];
            const float* fj = &force[(size_t)j * 3 * NF];
            float* fd = &fdelta[(size_t)i * 3 * NF];
            #pragma unroll
            for (int nt = 0; nt < 4; nt++) {
                int col = warp_n * 32 + nt * 8 + ((lane & 3) << 1);
                float v1a = p1r[mt][nt][half*2+0], v1b = p1r[mt][nt][half*2+1];
                float v2a = acc[mt][nt][half*2+0], v2b = acc[mt][nt][half*2+1];
                #pragma unroll
                for (int d = 0; d < 3; d++) {
                    float2 f = *(const float2*)&fj[d*NF + col];
                    atomicAdd(&fd[d*NF + col],     fmaf(v1a, ddir[d], v2a * f.x));
                    atomicAdd(&fd[d*NF + col + 1], fmaf(v1b, ddir[d], v2b * f.y));
                }
            }
        }
    }
}

// ---------------- g = force@euW fused with atom += sum_d force*g ----------------
// force reconstructed from the smem A tile (hi+lo) — no gmem re-read.
__global__ void __launch_bounds__(NTHR) gemm_atom_k(
    const bf16* __restrict__ Fhi, const bf16* __restrict__ Flo,
    const bf16* __restrict__ Whi, const bf16* __restrict__ Wlo,
    float* __restrict__ atom, int M)
{
    extern __shared__ char sm[];
    const uint32_t smb = smem_u32(sm);
    const int tid  = threadIdx.x;
    const int lane = tid & 31;
    const int warp = tid >> 5;
    const int warp_m = warp & 3;
    const int warp_n = warp >> 2;
    const int m0   = blockIdx.x * 128;

    load_tile_bounded(sm, SM_A, Fhi, Flo, m0, M, tid);
    load_tile_full(sm, SM_B, Whi, Wlo, tid);
    __syncthreads();

    float acc[2][4][4];
    do_mma_stage(smb, SM_A, SM_B, lane, warp_m, warp_n, acc);

    #pragma unroll
    for (int mt = 0; mt < 2; mt++) {
        #pragma unroll
        for (int half = 0; half < 2; half++) {
            int lrow = warp_m * 32 + mt * 16 + (lane >> 2) + half * 8;
            int r = m0 + lrow;
            if (r >= M) continue;
            int n = r / 3;
            #pragma unroll
            for (int nt = 0; nt < 4; nt++) {
                int col = warp_n * 32 + nt * 8 + ((lane & 3) << 1);
                uint32_t off = ((uint32_t)lrow * LDA + col) * 2;
                uint32_t ph = *(const uint32_t*)(sm + SM_A + off);
                uint32_t pl = *(const uint32_t*)(sm + SM_A + REG_B + off);
                float fx = __bfloat162float(__ushort_as_bfloat16((uint16_t)(ph & 0xFFFF)))
                         + __bfloat162float(__ushort_as_bfloat16((uint16_t)(pl & 0xFFFF)));
                float fy = __bfloat162float(__ushort_as_bfloat16((uint16_t)(ph >> 16)))
                         + __bfloat162float(__ushort_as_bfloat16((uint16_t)(pl >> 16)));
                atomicAdd(&atom[(size_t)n * NF + col],     acc[mt][nt][half*2+0] * fx);
                atomicAdd(&atom[(size_t)n * NF + col + 1], acc[mt][nt][half*2+1] * fy);
            }
        }
    }
}

// ---------------- init: atom = node_emb[z] (+ hi/lo emit) ----------------
__global__ void init_atom_k(const int* __restrict__ z, const float* __restrict__ emb,
                            float* __restrict__ atom, bf16* __restrict__ hi,
                            bf16* __restrict__ lo)
{
    int idx = blockIdx.x * blockDim.x + threadIdx.x;
    int n = idx >> 7, f = idx & 127;
    float v = emb[(size_t)z[n] * NF + f];
    atom[idx] = v;
    bf16 hb, lb; split_bf16(v, hb, lb);
    hi[idx] = hb; lo[idx] = lb;
}

// ---------------- edge embedding ----------------
__global__ void edge_embed_k(const float* __restrict__ pos, const int* __restrict__ ei,
                             float* __restrict__ dist, float* __restrict__ dir)
{
    int e = blockIdx.x * blockDim.x + threadIdx.x;
    if (e >= N_EDGES) return;
    int i = ei[e], j = ei[N_EDGES + e];
    float dx = pos[j*3+0] - pos[i*3+0];
    float dy = pos[j*3+1] - pos[i*3+1];
    float dz = pos[j*3+2] - pos[i*3+2];
    float d = sqrtf(dx*dx + dy*dy + dz*dz + 1e-12f);
    float inv = 1.0f / d;
    dir[e*3+0] = dx*inv; dir[e*3+1] = dy*inv; dir[e*3+2] = dz*inv;
    float fc = (d < CUTOFF_R) ? 0.5f * (cosf(3.14159265358979323846f * d / CUTOFF_R) + 1.0f) : 0.0f;
    const float inv_w = 1.0f / (CUTOFF_R / NB);
    #pragma unroll
    for (int b = 0; b < NB; b++) {
        float c = CUTOFF_R * (float)b / (float)(NB - 1);
        float t = (d - c) * inv_w;
        dist[(size_t)e*NB + b] = expf(-t*t) * fc;
    }
}

// ---------------- msg = (dist@meW)*h[i]*h[j] -> hi/lo; atom += segsum ----------------
__global__ void msg_k2(const float* __restrict__ h, const float* __restrict__ dist,
                       const int* __restrict__ ei, const float* __restrict__ meW,
                       bf16* __restrict__ mhi, bf16* __restrict__ mlo,
                       float* __restrict__ atom)
{
    __shared__ float sW[NB * NF];
    __shared__ float sd[32 * NB];
    int f = threadIdx.x;
    #pragma unroll
    for (int b = 0; b < NB; b++) sW[b*NF + f] = meW[b*NF + f];
    int e0 = blockIdx.x * 32;
    for (int q = f; q < 32 * NB; q += NF) sd[q] = dist[(size_t)e0 * NB + q];
    __syncthreads();
    #pragma unroll 2
    for (int t = 0; t < 32; t++) {
        int e = e0 + t;
        int i = ei[e], j = ei[N_EDGES + e];
        float me = 0.f;
        #pragma unroll
        for (int b = 0; b < NB; b++) me = fmaf(sd[t*NB + b], sW[b*NF + f], me);
        float m = me * h[(size_t)i*NF + f] * h[(size_t)j*NF + f];
        bf16 hb, lb; split_bf16(m, hb, lb);
        mhi[(size_t)e*NF + f] = hb;
        mlo[(size_t)e*NF + f] = lb;
        atomicAdd(&atom[(size_t)i*NF + f], m);
    }
}

// ---------------- force += fdelta; fdelta=0; emit hi/lo ----------------
__global__ void force_update_k2(float* __restrict__ force, float* __restrict__ fdelta,
                                bf16* __restrict__ fhi, bf16* __restrict__ flo)
{
    int idx = blockIdx.x * blockDim.x + threadIdx.x;
    float v = force[idx] + fdelta[idx];
    force[idx] = v;
    fdelta[idx] = 0.f;
    bf16 hb, lb; split_bf16(v, hb, lb);
    fhi[idx] = hb; flo[idx] = lb;
}

// ---------------- host ----------------
extern "C" void kernel_launch(void* const* d_in, const int* in_sizes, int n_in,
                              void* d_out, int out_size)
{
    const int*   z        = (const int*)  d_in[0];
    const float* pos      = (const float*)d_in[1];
    const int*   ei       = (const int*)  d_in[4];
    const float* node_emb = (const float*)d_in[5];
    const float* mnp_W1   = (const float*)d_in[6];
    const float* mnp_b1   = (const float*)d_in[7];
    const float* mnp_W2   = (const float*)d_in[8];
    const float* mnp_b2   = (const float*)d_in[9];
    const float* me_W     = (const float*)d_in[10];
    const float* em1_W1   = (const float*)d_in[11];
    const float* em1_W2   = (const float*)d_in[12];
    const float* em2_W1   = (const float*)d_in[13];
    const float* em2_W2   = (const float*)d_in[14];
    const float* eu_W     = (const float*)d_in[15];

    float* atom = (float*)d_out;
    float* force;

    float *dist, *dir, *h, *fdelta, *force_fb;
    bf16 *bhi1, *blo1, *bhi2, *blo2, *whi, *wlo;
    cudaGetSymbolAddress((void**)&dist,     g_dist);
    cudaGetSymbolAddress((void**)&dir,      g_dir);
    cudaGetSymbolAddress((void**)&h,        g_h);
    cudaGetSymbolAddress((void**)&fdelta,   g_fdelta);
    cudaGetSymbolAddress((void**)&force_fb, g_force_fb);
    cudaGetSymbolAddress((void**)&bhi1, g_bhi1);
    cudaGetSymbolAddress((void**)&blo1, g_blo1);
    cudaGetSymbolAddress((void**)&bhi2, g_bhi2);
    cudaGetSymbolAddress((void**)&blo2, g_blo2);
    cudaGetSymbolAddress((void**)&whi,  g_whi);
    cudaGetSymbolAddress((void**)&wlo,  g_wlo);

    if (out_size >= N_NODES * (NF + 3 * NF)) force = atom + (size_t)N_NODES * NF;
    else                                     force = force_fb;

    cudaFuncSetAttribute(fused_chain1_k,   cudaFuncAttributeMaxDynamicSharedMemorySize, FUSED_SM);
    cudaFuncSetAttribute(chain2_scatter_k, cudaFuncAttributeMaxDynamicSharedMemorySize, FUSED_SM);
    cudaFuncSetAttribute(gemm_atom_k,      cudaFuncAttributeMaxDynamicSharedMemorySize, GA_SM);
    cudaFuncSetAttribute(prep_all_k,       cudaFuncAttributeMaxDynamicSharedMemorySize, PREP_SM);

    prep_all_k<<<21, 256, PREP_SM>>>(mnp_W1, mnp_W2, em1_W1, em1_W2, em2_W1, em2_W2, eu_W,
                                     whi, wlo);

    cudaMemsetAsync(force,  0, (size_t)N_NODES * 3 * NF * sizeof(float), 0);
    cudaMemsetAsync(fdelta, 0, (size_t)N_NODES * 3 * NF * sizeof(float), 0);

    init_atom_k<<<(N_NODES * NF) / 256, 256>>>(z, node_emb, atom, bhi1, blo1);
    edge_embed_k<<<(N_EDGES + 255) / 256, 256>>>(pos, ei, dist, dir);

    const int GN  = (N_NODES + 127) / 128;       // 79
    const int GE  = N_EDGES / 128;               // 1250
    const int GF3 = (N_NODES * 3 + 127) / 128;   // 235

    for (int l = 0; l < NLAYERS; l++) {
        const bf16* Whi = whi + (size_t)l * 7 * 16384;
        const bf16* Wlo = wlo + (size_t)l * 7 * 16384;
        const float* b1 = mnp_b1 + (size_t)l * NF;
        const float* b2 = mnp_b2 + (size_t)l * NF;
        const float* mW = me_W   + (size_t)l * NB * NF;

        // atom -> hi/lo (layer 0 handled by init_atom_k)
        if (l > 0)
            conv_k<<<(N_NODES * NF / 4 + 255) / 256, 256>>>(atom, bhi1, blo1, N_NODES * NF / 4);

        // h = silu(atom@W1+b1)@W2+b2
        fused_chain1_k<<<GN, NTHR, FUSED_SM>>>(
            bhi1, blo1,
            Whi + 0*16384, Wlo + 0*16384, Whi + 1*16384, Wlo + 1*16384,
            b1, b2, h, N_NODES);

        // msg (hi/lo) + atom segsum
        msg_k2<<<N_EDGES / 32, NF>>>(h, dist, ei, mW, bhi1, blo1, atom);

        // fused: p1/p2 chains + scatter into fdelta
        chain2_scatter_k<<<GE, NTHR, FUSED_SM>>>(
            bhi1, blo1,
            Whi + 2*16384, Wlo + 2*16384, Whi + 3*16384, Wlo + 3*16384,
            Whi + 4*16384, Wlo + 4*16384, Whi + 5*16384, Wlo + 5*16384,
            ei, dir, force, fdelta);

        // force += fdelta; emits hi/lo
        force_update_k2<<<(N_NODES * 3 * NF) / 256, 256>>>(force, fdelta, bhi2, blo2);

        // atom += sum_d force * (force@euW)   (force from smem hi+lo)
        gemm_atom_k<<<GF3, NTHR, GA_SM>>>(bhi2, blo2, Whi + 6*16384, Wlo + 6*16384,
                                          atom, N_NODES * 3);
    }
}